// round 6
// baseline (speedup 1.0000x reference)
#include <cuda_runtime.h>
#include <cuda_bf16.h>
#include <cstdint>

// ---------------------------------------------------------------------------
// WindowAttention (Swin): B=2048 windows, N=49 tokens, DIM=384, HEADS=12, hd=32
// R6: GEMM -> 256x128 CTA / 64x64 warp tiles, 3-stage cp.async (dynamic smem).
//     Attention -> register-blocked 4x4 tiles, transposed Q/K smem (float4
//     loads), parallel softmax.
// ---------------------------------------------------------------------------

#define BDIM   384
#define HEADS  12
#define HD     32
#define NTOK   49
#define NWIN   2048
#define NMASK  64
#define MROWS  (NWIN * NTOK)        // 100352
#define QKVN   (3 * BDIM)           // 1152

__device__ float g_qkv[(size_t)MROWS * QKVN];    // ~462 MB
__device__ float g_attn[(size_t)MROWS * BDIM];   // ~154 MB

__device__ __forceinline__ uint32_t cvt_tf32(float x) {
    uint32_t r;
    asm("cvt.rna.tf32.f32 %0, %1;" : "=r"(r) : "f"(x));
    return r;
}
__device__ __forceinline__ uint32_t smem_u32(const void* p) {
    uint32_t r;
    asm("{ .reg .u64 t; cvta.to.shared.u64 t, %1; cvt.u32.u64 %0, t; }"
        : "=r"(r) : "l"(p));
    return r;
}
#define CP_ASYNC16(dst_u32, src_ptr) \
    asm volatile("cp.async.cg.shared.global [%0], [%1], 16;" :: "r"(dst_u32), "l"(src_ptr))
#define CP_COMMIT() asm volatile("cp.async.commit_group;" ::: "memory")
#define CP_WAIT1()  asm volatile("cp.async.wait_group 1;" ::: "memory")

// ---------------------------------------------------------------------------
// TF32 GEMM: C[m][n] = sum_k A[m][k]*W[n][k] + bias[n]
// A:[M,K] row-major, W:[N,K] row-major. M%256==0, N%128==0, K%16==0.
// 256x128 CTA tile, 8 warps (4x2) of 64x64. 3-stage cp.async pipeline.
// ---------------------------------------------------------------------------
__global__ __launch_bounds__(256, 1)
void tf32_gemm_abT_bias(const float* __restrict__ A,
                        const float* __restrict__ W,
                        const float* __restrict__ bias,
                        float* __restrict__ C,
                        int M, int N, int K) {
    constexpr int BM = 256, BN = 128, BK = 16, LD = 20;
    extern __shared__ float smem[];
    float* As = smem;                       // [3][BM][LD]
    float* Bs = smem + 3 * BM * LD;         // [3][BN][LD]

    const int tid = threadIdx.x;
    const int bm = blockIdx.y * BM;
    const int bn = blockIdx.x * BN;
    const int lane = tid & 31;
    const int warp = tid >> 5;
    const int wm = (warp >> 1) * 64;        // 0,64,128,192
    const int wn = (warp & 1) * 64;         // 0,64
    const int g   = lane >> 2;              // 0..7
    const int tig = lane & 3;               // 0..3

    float acc[4][8][4];
#pragma unroll
    for (int mt = 0; mt < 4; mt++)
#pragma unroll
        for (int nt = 0; nt < 8; nt++)
#pragma unroll
            for (int e = 0; e < 4; e++) acc[mt][nt][e] = 0.0f;

    const int KT = K / BK;

    auto load_stage = [&](int st, int kt) {
        const int k0 = kt * BK;
        float* as = As + st * (BM * LD);
        float* bs = Bs + st * (BN * LD);
#pragma unroll
        for (int i = 0; i < 4; i++) {
            int idx = tid + i * 256;
            int r = idx >> 2, s4 = (idx & 3) * 4;
            CP_ASYNC16(smem_u32(&as[r * LD + s4]),
                       A + (size_t)(bm + r) * K + k0 + s4);
        }
#pragma unroll
        for (int i = 0; i < 2; i++) {
            int idx = tid + i * 256;
            int r = idx >> 2, s4 = (idx & 3) * 4;
            CP_ASYNC16(smem_u32(&bs[r * LD + s4]),
                       W + (size_t)(bn + r) * K + k0 + s4);
        }
    };

    auto compute = [&](int st) {
        const float* as = As + st * (BM * LD);
        const float* bs = Bs + st * (BN * LD);
#pragma unroll
        for (int ks = 0; ks < 2; ks++) {
            const int kk = ks * 8 + tig;
            uint32_t a[4][4], bf[8][2];
#pragma unroll
            for (int mt = 0; mt < 4; mt++) {
                int r0 = wm + mt * 16 + g;
                a[mt][0] = cvt_tf32(as[r0 * LD + kk]);
                a[mt][1] = cvt_tf32(as[(r0 + 8) * LD + kk]);
                a[mt][2] = cvt_tf32(as[r0 * LD + kk + 4]);
                a[mt][3] = cvt_tf32(as[(r0 + 8) * LD + kk + 4]);
            }
#pragma unroll
            for (int nt = 0; nt < 8; nt++) {
                int c0 = wn + nt * 8 + g;
                bf[nt][0] = cvt_tf32(bs[c0 * LD + kk]);
                bf[nt][1] = cvt_tf32(bs[c0 * LD + kk + 4]);
            }
#pragma unroll
            for (int mt = 0; mt < 4; mt++)
#pragma unroll
                for (int nt = 0; nt < 8; nt++) {
                    float* c = acc[mt][nt];
                    asm volatile(
                        "mma.sync.aligned.m16n8k8.row.col.f32.tf32.tf32.f32 "
                        "{%0,%1,%2,%3}, {%4,%5,%6,%7}, {%8,%9}, {%0,%1,%2,%3};"
                        : "+f"(c[0]), "+f"(c[1]), "+f"(c[2]), "+f"(c[3])
                        : "r"(a[mt][0]), "r"(a[mt][1]), "r"(a[mt][2]), "r"(a[mt][3]),
                          "r"(bf[nt][0]), "r"(bf[nt][1]));
                }
        }
    };

    load_stage(0, 0); CP_COMMIT();
    load_stage(1, 1); CP_COMMIT();

    for (int kt = 0; kt < KT; kt++) {
        CP_WAIT1();
        __syncthreads();
        compute(kt % 3);
        if (kt + 2 < KT) load_stage((kt + 2) % 3, kt + 2);
        CP_COMMIT();
    }

#pragma unroll
    for (int mt = 0; mt < 4; mt++) {
#pragma unroll
        for (int nt = 0; nt < 8; nt++) {
            int row = bm + wm + mt * 16 + g;
            int col = bn + wn + nt * 8 + 2 * tig;
            float b0 = bias[col], b1 = bias[col + 1];
            float2 o0 = {acc[mt][nt][0] + b0, acc[mt][nt][1] + b1};
            float2 o1 = {acc[mt][nt][2] + b0, acc[mt][nt][3] + b1};
            *(float2*)(C + (size_t)row * N + col) = o0;
            *(float2*)(C + (size_t)(row + 8) * N + col) = o1;
        }
    }
}

// ---------------------------------------------------------------------------
// Fused attention per (window, head): register-blocked 4x4 tiles.
//   Q,K stored transposed [d][token] (float4 along tokens),
//   V row-major [token][d] stride 32 (conflict-free for PV),
//   S [52][53].
// ---------------------------------------------------------------------------
__global__ __launch_bounds__(128)
void attn_kernel(const float* __restrict__ mask,
                 const float* __restrict__ rel_table,
                 const int*   __restrict__ rel_index) {
    const int b = blockIdx.x;   // window
    const int h = blockIdx.y;   // head

    __shared__ float qt[HD][52];      // [d][i]
    __shared__ float ktr[HD][52];     // [d][j]
    __shared__ float vsm[52][HD];     // [j][d]
    __shared__ float s[52 * 53];

    const int tid = threadIdx.x;
    const float scale = 0.17677669529663687f;  // 32^-0.5

    const float* base = g_qkv + (size_t)b * NTOK * QKVN + h * HD;
    for (int e = tid; e < NTOK * HD; e += 128) {
        int i = e >> 5, d = e & 31;
        const float* p = base + i * QKVN + d;
        qt[d][i]  = p[0];
        ktr[d][i] = p[BDIM];
        vsm[i][d] = p[2 * BDIM];
    }
    __syncthreads();

    // Scores: 13x13 grid of 4x4 tiles (padded to 52), guard writes to <49.
    const float* mrow = mask + (size_t)(b & (NMASK - 1)) * (NTOK * NTOK);
    for (int tt = tid; tt < 169; tt += 128) {
        int ig = tt / 13, jg = tt - ig * 13;
        int i0 = ig * 4, j0 = jg * 4;
        float acc[4][4];
#pragma unroll
        for (int r = 0; r < 4; r++)
#pragma unroll
            for (int c = 0; c < 4; c++) acc[r][c] = 0.0f;

#pragma unroll 8
        for (int d = 0; d < HD; d++) {
            float qv[4], kv[4];
            *(float4*)qv = *(const float4*)&qt[d][i0];
            *(float4*)kv = *(const float4*)&ktr[d][j0];
#pragma unroll
            for (int r = 0; r < 4; r++)
#pragma unroll
                for (int c = 0; c < 4; c++)
                    acc[r][c] = fmaf(qv[r], kv[c], acc[r][c]);
        }
#pragma unroll
        for (int r = 0; r < 4; r++) {
            int i = i0 + r;
            if (i >= NTOK) continue;
#pragma unroll
            for (int c = 0; c < 4; c++) {
                int j = j0 + c;
                if (j >= NTOK) continue;
                int e = i * NTOK + j;
                float bias = rel_table[rel_index[e] * HEADS + h];
                s[i * 53 + j] = acc[r][c] * scale + bias + mrow[e];
            }
        }
    }
    __syncthreads();

    // Softmax: 2 lanes per row (lane pair t, t^1), shfl combine.
    {
        int i = tid >> 1, half = tid & 1;
        bool act = (i < NTOK);
        int j0 = half * 25;
        int cnt = act ? (half ? 24 : 25) : 0;
        float m = -1e30f;
        for (int jj = 0; jj < cnt; jj++) m = fmaxf(m, s[i * 53 + j0 + jj]);
        m = fmaxf(m, __shfl_xor_sync(0xffffffffu, m, 1));
        float sum = 0.0f;
        for (int jj = 0; jj < cnt; jj++) {
            float e = __expf(s[i * 53 + j0 + jj] - m);
            s[i * 53 + j0 + jj] = e;
            sum += e;
        }
        sum += __shfl_xor_sync(0xffffffffu, sum, 1);
        float inv = 1.0f / sum;
        for (int jj = 0; jj < cnt; jj++) s[i * 53 + j0 + jj] *= inv;
    }
    __syncthreads();

    // PV: out[49,32] as 13x8 grid of 4x4 tiles; one tile per thread (tid<104).
    if (tid < 104) {
        int ig = tid >> 3, dg = tid & 7;
        int i0 = ig * 4, d0 = dg * 4;
        float acc[4][4];
#pragma unroll
        for (int r = 0; r < 4; r++)
#pragma unroll
            for (int c = 0; c < 4; c++) acc[r][c] = 0.0f;

#pragma unroll 7
        for (int j = 0; j < NTOK; j++) {
            float sv[4];
#pragma unroll
            for (int r = 0; r < 4; r++) sv[r] = s[(i0 + r) * 53 + j];
            float vv[4];
            *(float4*)vv = *(const float4*)&vsm[j][d0];
#pragma unroll
            for (int r = 0; r < 4; r++)
#pragma unroll
                for (int c = 0; c < 4; c++)
                    acc[r][c] = fmaf(sv[r], vv[c], acc[r][c]);
        }
        float* outb = g_attn + (size_t)b * NTOK * BDIM + h * HD + d0;
#pragma unroll
        for (int r = 0; r < 4; r++) {
            int i = i0 + r;
            if (i < NTOK) {
                float4 o = {acc[r][0], acc[r][1], acc[r][2], acc[r][3]};
                *(float4*)(outb + (size_t)i * BDIM) = o;
            }
        }
    }
}

// ---------------------------------------------------------------------------
extern "C" void kernel_launch(void* const* d_in, const int* in_sizes, int n_in,
                              void* d_out, int out_size) {
    const float* x         = (const float*)d_in[0];  // [2048, 49, 384]
    const float* mask      = (const float*)d_in[1];  // [64, 49, 49]
    const float* qkv_w     = (const float*)d_in[2];  // [1152, 384]
    const float* qkv_b     = (const float*)d_in[3];  // [1152]
    const float* proj_w    = (const float*)d_in[4];  // [384, 384]
    const float* proj_b    = (const float*)d_in[5];  // [384]
    const float* rel_table = (const float*)d_in[6];  // [169, 12]
    const int*   rel_index = (const int*)d_in[7];    // [49, 49]
    float* out = (float*)d_out;                      // [2048, 49, 384]

    float* qkv_buf;
    float* attn_buf;
    cudaGetSymbolAddress((void**)&qkv_buf, g_qkv);
    cudaGetSymbolAddress((void**)&attn_buf, g_attn);

    const int SMEM_GEMM = (3 * 256 * 20 + 3 * 128 * 20) * 4;  // 92160 B
    cudaFuncSetAttribute(tf32_gemm_abT_bias,
                         cudaFuncAttributeMaxDynamicSharedMemorySize, SMEM_GEMM);

    // 1) QKV GEMM: [100352, 384] @ [1152, 384]^T -> [100352, 1152]
    {
        dim3 grid(QKVN / 128, MROWS / 256);   // (9, 392)
        tf32_gemm_abT_bias<<<grid, 256, SMEM_GEMM>>>(x, qkv_w, qkv_b, qkv_buf,
                                                     MROWS, QKVN, BDIM);
    }

    // 2) attention per (window, head)
    {
        dim3 grid(NWIN, HEADS);               // (2048, 12)
        attn_kernel<<<grid, 128>>>(mask, rel_table, rel_index);
    }

    // 3) proj GEMM: [100352, 384] @ [384, 384]^T -> [100352, 384]
    {
        dim3 grid(BDIM / 128, MROWS / 256);   // (3, 392)
        tf32_gemm_abT_bias<<<grid, 256, SMEM_GEMM>>>(attn_buf, proj_w, proj_b, out,
                                                     MROWS, BDIM, BDIM);
    }
}

// round 7
// speedup vs baseline: 1.0597x; 1.0597x over previous
#include <cuda_runtime.h>
#include <cuda_bf16.h>
#include <cstdint>

// ---------------------------------------------------------------------------
// WindowAttention (Swin): B=2048 windows, N=49 tokens, DIM=384, HEADS=12, hd=32
// R7: GEMM back to 128x128 (2 CTA/SM) but BK=32 and NO in-loop cvt: all GEMM
//     inputs pre-rounded to TF32-RN in memory (prep kernels + fused rounding
//     in attention epilogue). Attention: R6 register-blocked version.
// ---------------------------------------------------------------------------

#define BDIM   384
#define HEADS  12
#define HD     32
#define NTOK   49
#define NWIN   2048
#define NMASK  64
#define MROWS  (NWIN * NTOK)        // 100352
#define QKVN   (3 * BDIM)           // 1152

__device__ float g_qkv[(size_t)MROWS * QKVN];    // ~462 MB
__device__ float g_attn[(size_t)MROWS * BDIM];   // ~154 MB  (pre-rounded tf32)
__device__ float g_xr[(size_t)MROWS * BDIM];     // ~154 MB  x rounded to tf32
__device__ float g_wq[QKVN * BDIM];              // qkv_w rounded
__device__ float g_wp[BDIM * BDIM];              // proj_w rounded

__device__ __forceinline__ uint32_t cvt_tf32(float x) {
    uint32_t r;
    asm("cvt.rna.tf32.f32 %0, %1;" : "=r"(r) : "f"(x));
    return r;
}
__device__ __forceinline__ float round_tf32f(float x) {
    return __uint_as_float(cvt_tf32(x));
}
__device__ __forceinline__ uint32_t smem_u32(const void* p) {
    uint32_t r;
    asm("{ .reg .u64 t; cvta.to.shared.u64 t, %1; cvt.u32.u64 %0, t; }"
        : "=r"(r) : "l"(p));
    return r;
}
#define CP_ASYNC16(dst_u32, src_ptr) \
    asm volatile("cp.async.cg.shared.global [%0], [%1], 16;" :: "r"(dst_u32), "l"(src_ptr))
#define CP_COMMIT() asm volatile("cp.async.commit_group;" ::: "memory")
#define CP_WAIT1()  asm volatile("cp.async.wait_group 1;" ::: "memory")

// ---------------------------------------------------------------------------
// Prep: elementwise round fp32 -> tf32(RN), float4 grid-stride. n % 4 == 0.
// ---------------------------------------------------------------------------
__global__ void round_tf32_kernel(const float* __restrict__ src,
                                  float* __restrict__ dst, int n4) {
    int i = blockIdx.x * blockDim.x + threadIdx.x;
    if (i < n4) {
        float4 v = ((const float4*)src)[i];
        v.x = round_tf32f(v.x); v.y = round_tf32f(v.y);
        v.z = round_tf32f(v.z); v.w = round_tf32f(v.w);
        ((float4*)dst)[i] = v;
    }
}

// ---------------------------------------------------------------------------
// TF32 GEMM (inputs already tf32-rounded): C[m][n]=sum_k A[m][k]*W[n][k]+bias[n]
// A:[M,K] row-major, W:[N,K] row-major. M%128==0, N%128==0, K%32==0.
// 128x128x32 CTA tile, 8 warps (4x2) of 32x64, 2-stage cp.async.
// ---------------------------------------------------------------------------
__global__ __launch_bounds__(256, 2)
void tf32_gemm_abT_bias(const float* __restrict__ A,
                        const float* __restrict__ W,
                        const float* __restrict__ bias,
                        float* __restrict__ C,
                        int M, int N, int K) {
    constexpr int BM = 128, BN = 128, BK = 32, LD = 36;
    extern __shared__ float smem[];
    float* As = smem;                       // [2][BM][LD]
    float* Bs = smem + 2 * BM * LD;         // [2][BN][LD]

    const int tid = threadIdx.x;
    const int bm = blockIdx.y * BM;
    const int bn = blockIdx.x * BN;
    const int lane = tid & 31;
    const int warp = tid >> 5;
    const int wm = (warp >> 1) * 32;        // 0,32,64,96
    const int wn = (warp & 1) * 64;         // 0,64
    const int g   = lane >> 2;              // 0..7
    const int tig = lane & 3;               // 0..3

    float acc[2][8][4];
#pragma unroll
    for (int mt = 0; mt < 2; mt++)
#pragma unroll
        for (int nt = 0; nt < 8; nt++)
#pragma unroll
            for (int e = 0; e < 4; e++) acc[mt][nt][e] = 0.0f;

    const int KT = K / BK;   // 12

    auto load_stage = [&](int st, int kt) {
        const int k0 = kt * BK;
        float* as = As + st * (BM * LD);
        float* bs = Bs + st * (BN * LD);
#pragma unroll
        for (int i = 0; i < 4; i++) {
            int idx = tid + i * 256;        // 0..1023
            int r = idx >> 3, s4 = (idx & 7) * 4;
            CP_ASYNC16(smem_u32(&as[r * LD + s4]),
                       A + (size_t)(bm + r) * K + k0 + s4);
        }
#pragma unroll
        for (int i = 0; i < 4; i++) {
            int idx = tid + i * 256;
            int r = idx >> 3, s4 = (idx & 7) * 4;
            CP_ASYNC16(smem_u32(&bs[r * LD + s4]),
                       W + (size_t)(bn + r) * K + k0 + s4);
        }
    };

    auto compute = [&](int st) {
        const float* as = As + st * (BM * LD);
        const float* bs = Bs + st * (BN * LD);
#pragma unroll
        for (int ks = 0; ks < 4; ks++) {
            const int kk = ks * 8 + tig;
            uint32_t a[2][4], bf[8][2];
#pragma unroll
            for (int mt = 0; mt < 2; mt++) {
                int r0 = wm + mt * 16 + g;
                a[mt][0] = __float_as_uint(as[r0 * LD + kk]);
                a[mt][1] = __float_as_uint(as[(r0 + 8) * LD + kk]);
                a[mt][2] = __float_as_uint(as[r0 * LD + kk + 4]);
                a[mt][3] = __float_as_uint(as[(r0 + 8) * LD + kk + 4]);
            }
#pragma unroll
            for (int nt = 0; nt < 8; nt++) {
                int c0 = wn + nt * 8 + g;
                bf[nt][0] = __float_as_uint(bs[c0 * LD + kk]);
                bf[nt][1] = __float_as_uint(bs[c0 * LD + kk + 4]);
            }
#pragma unroll
            for (int mt = 0; mt < 2; mt++)
#pragma unroll
                for (int nt = 0; nt < 8; nt++) {
                    float* c = acc[mt][nt];
                    asm volatile(
                        "mma.sync.aligned.m16n8k8.row.col.f32.tf32.tf32.f32 "
                        "{%0,%1,%2,%3}, {%4,%5,%6,%7}, {%8,%9}, {%0,%1,%2,%3};"
                        : "+f"(c[0]), "+f"(c[1]), "+f"(c[2]), "+f"(c[3])
                        : "r"(a[mt][0]), "r"(a[mt][1]), "r"(a[mt][2]), "r"(a[mt][3]),
                          "r"(bf[nt][0]), "r"(bf[nt][1]));
                }
        }
    };

    load_stage(0, 0);
    CP_COMMIT();

    for (int kt = 0; kt < KT; kt++) {
        if (kt + 1 < KT) load_stage((kt + 1) & 1, kt + 1);
        CP_COMMIT();
        CP_WAIT1();
        __syncthreads();
        compute(kt & 1);
        __syncthreads();
    }

#pragma unroll
    for (int mt = 0; mt < 2; mt++) {
#pragma unroll
        for (int nt = 0; nt < 8; nt++) {
            int row = bm + wm + mt * 16 + g;
            int col = bn + wn + nt * 8 + 2 * tig;
            float b0 = bias[col], b1 = bias[col + 1];
            float2 o0 = {acc[mt][nt][0] + b0, acc[mt][nt][1] + b1};
            float2 o1 = {acc[mt][nt][2] + b0, acc[mt][nt][3] + b1};
            *(float2*)(C + (size_t)row * N + col) = o0;
            *(float2*)(C + (size_t)(row + 8) * N + col) = o1;
        }
    }
}

// ---------------------------------------------------------------------------
// Fused attention per (window, head): register-blocked 4x4 tiles.
// Output stored pre-rounded to tf32 (feeds proj GEMM).
// ---------------------------------------------------------------------------
__global__ __launch_bounds__(128)
void attn_kernel(const float* __restrict__ mask,
                 const float* __restrict__ rel_table,
                 const int*   __restrict__ rel_index) {
    const int b = blockIdx.x;   // window
    const int h = blockIdx.y;   // head

    __shared__ float qt[HD][52];      // [d][i]
    __shared__ float ktr[HD][52];     // [d][j]
    __shared__ float vsm[52][HD];     // [j][d]
    __shared__ float s[52 * 53];

    const int tid = threadIdx.x;
    const float scale = 0.17677669529663687f;  // 32^-0.5

    const float* base = g_qkv + (size_t)b * NTOK * QKVN + h * HD;
    for (int e = tid; e < NTOK * HD; e += 128) {
        int i = e >> 5, d = e & 31;
        const float* p = base + i * QKVN + d;
        qt[d][i]  = p[0];
        ktr[d][i] = p[BDIM];
        vsm[i][d] = p[2 * BDIM];
    }
    __syncthreads();

    // Scores: 13x13 grid of 4x4 tiles (padded to 52), guard writes to <49.
    const float* mrow = mask + (size_t)(b & (NMASK - 1)) * (NTOK * NTOK);
    for (int tt = tid; tt < 169; tt += 128) {
        int ig = tt / 13, jg = tt - ig * 13;
        int i0 = ig * 4, j0 = jg * 4;
        float acc[4][4];
#pragma unroll
        for (int r = 0; r < 4; r++)
#pragma unroll
            for (int c = 0; c < 4; c++) acc[r][c] = 0.0f;

#pragma unroll 8
        for (int d = 0; d < HD; d++) {
            float qv[4], kv[4];
            *(float4*)qv = *(const float4*)&qt[d][i0];
            *(float4*)kv = *(const float4*)&ktr[d][j0];
#pragma unroll
            for (int r = 0; r < 4; r++)
#pragma unroll
                for (int c = 0; c < 4; c++)
                    acc[r][c] = fmaf(qv[r], kv[c], acc[r][c]);
        }
#pragma unroll
        for (int r = 0; r < 4; r++) {
            int i = i0 + r;
            if (i >= NTOK) continue;
#pragma unroll
            for (int c = 0; c < 4; c++) {
                int j = j0 + c;
                if (j >= NTOK) continue;
                int e = i * NTOK + j;
                float bias = rel_table[rel_index[e] * HEADS + h];
                s[i * 53 + j] = acc[r][c] * scale + bias + mrow[e];
            }
        }
    }
    __syncthreads();

    // Softmax: 2 lanes per row, shfl combine.
    {
        int i = tid >> 1, half = tid & 1;
        bool act = (i < NTOK);
        int j0 = half * 25;
        int cnt = act ? (half ? 24 : 25) : 0;
        float m = -1e30f;
        for (int jj = 0; jj < cnt; jj++) m = fmaxf(m, s[i * 53 + j0 + jj]);
        m = fmaxf(m, __shfl_xor_sync(0xffffffffu, m, 1));
        float sum = 0.0f;
        for (int jj = 0; jj < cnt; jj++) {
            float e = __expf(s[i * 53 + j0 + jj] - m);
            s[i * 53 + j0 + jj] = e;
            sum += e;
        }
        sum += __shfl_xor_sync(0xffffffffu, sum, 1);
        float inv = 1.0f / sum;
        for (int jj = 0; jj < cnt; jj++) s[i * 53 + j0 + jj] *= inv;
    }
    __syncthreads();

    // PV: out[49,32] as 13x8 grid of 4x4 tiles; one tile per thread (tid<104).
    if (tid < 104) {
        int ig = tid >> 3, dg = tid & 7;
        int i0 = ig * 4, d0 = dg * 4;
        float acc[4][4];
#pragma unroll
        for (int r = 0; r < 4; r++)
#pragma unroll
            for (int c = 0; c < 4; c++) acc[r][c] = 0.0f;

#pragma unroll 7
        for (int j = 0; j < NTOK; j++) {
            float sv[4];
#pragma unroll
            for (int r = 0; r < 4; r++) sv[r] = s[(i0 + r) * 53 + j];
            float vv[4];
            *(float4*)vv = *(const float4*)&vsm[j][d0];
#pragma unroll
            for (int r = 0; r < 4; r++)
#pragma unroll
                for (int c = 0; c < 4; c++)
                    acc[r][c] = fmaf(sv[r], vv[c], acc[r][c]);
        }
        float* outb = g_attn + (size_t)b * NTOK * BDIM + h * HD + d0;
#pragma unroll
        for (int r = 0; r < 4; r++) {
            int i = i0 + r;
            if (i < NTOK) {
                float4 o = {round_tf32f(acc[r][0]), round_tf32f(acc[r][1]),
                            round_tf32f(acc[r][2]), round_tf32f(acc[r][3])};
                *(float4*)(outb + (size_t)i * BDIM) = o;
            }
        }
    }
}

// ---------------------------------------------------------------------------
extern "C" void kernel_launch(void* const* d_in, const int* in_sizes, int n_in,
                              void* d_out, int out_size) {
    const float* x         = (const float*)d_in[0];  // [2048, 49, 384]
    const float* mask      = (const float*)d_in[1];  // [64, 49, 49]
    const float* qkv_w     = (const float*)d_in[2];  // [1152, 384]
    const float* qkv_b     = (const float*)d_in[3];  // [1152]
    const float* proj_w    = (const float*)d_in[4];  // [384, 384]
    const float* proj_b    = (const float*)d_in[5];  // [384]
    const float* rel_table = (const float*)d_in[6];  // [169, 12]
    const int*   rel_index = (const int*)d_in[7];    // [49, 49]
    float* out = (float*)d_out;                      // [2048, 49, 384]

    float *qkv_buf, *attn_buf, *xr, *wq, *wp;
    cudaGetSymbolAddress((void**)&qkv_buf, g_qkv);
    cudaGetSymbolAddress((void**)&attn_buf, g_attn);
    cudaGetSymbolAddress((void**)&xr, g_xr);
    cudaGetSymbolAddress((void**)&wq, g_wq);
    cudaGetSymbolAddress((void**)&wp, g_wp);

    const int SMEM_GEMM = (2 * 128 * 36 + 2 * 128 * 36) * 4;  // 73728 B
    cudaFuncSetAttribute(tf32_gemm_abT_bias,
                         cudaFuncAttributeMaxDynamicSharedMemorySize, SMEM_GEMM);

    // 0) Round GEMM inputs to TF32-RN once.
    {
        int n4 = (MROWS * BDIM) / 4;                 // 9,633,792
        round_tf32_kernel<<<(n4 + 255) / 256, 256>>>(x, xr, n4);
        int w4 = (QKVN * BDIM) / 4;
        round_tf32_kernel<<<(w4 + 255) / 256, 256>>>(qkv_w, wq, w4);
        int p4 = (BDIM * BDIM) / 4;
        round_tf32_kernel<<<(p4 + 255) / 256, 256>>>(proj_w, wp, p4);
    }

    // 1) QKV GEMM: [100352, 384] @ [1152, 384]^T -> [100352, 1152]
    {
        dim3 grid(QKVN / 128, MROWS / 128);   // (9, 784)
        tf32_gemm_abT_bias<<<grid, 256, SMEM_GEMM>>>(xr, wq, qkv_b, qkv_buf,
                                                     MROWS, QKVN, BDIM);
    }

    // 2) attention per (window, head)
    {
        dim3 grid(NWIN, HEADS);               // (2048, 12)
        attn_kernel<<<grid, 128>>>(mask, rel_table, rel_index);
    }

    // 3) proj GEMM: [100352, 384] @ [384, 384]^T -> [100352, 384]
    {
        dim3 grid(BDIM / 128, MROWS / 128);   // (3, 784)
        tf32_gemm_abT_bias<<<grid, 256, SMEM_GEMM>>>(attn_buf, wp, proj_b, out,
                                                     MROWS, BDIM, BDIM);
    }
}

// round 8
// speedup vs baseline: 1.0603x; 1.0006x over previous
#include <cuda_runtime.h>
#include <cuda_bf16.h>
#include <cstdint>

// ---------------------------------------------------------------------------
// WindowAttention (Swin): B=2048 windows, N=49 tokens, DIM=384, HEADS=12, hd=32
// R8: GEMM = R5 shape (128x128x16, static smem, 2-stage) with inputs
//     pre-rounded to TF32 (no in-loop cvt). Attention: precomputed
//     bias+mask table (kills per-CTA gathers), float4 gmem loads.
// ---------------------------------------------------------------------------

#define BDIM   384
#define HEADS  12
#define HD     32
#define NTOK   49
#define NWIN   2048
#define NMASK  64
#define MROWS  (NWIN * NTOK)        // 100352
#define QKVN   (3 * BDIM)           // 1152
#define NN     (NTOK * NTOK)        // 2401

__device__ float g_qkv[(size_t)MROWS * QKVN];    // ~462 MB
__device__ float g_attn[(size_t)MROWS * BDIM];   // ~154 MB (tf32-rounded)
__device__ float g_xr[(size_t)MROWS * BDIM];     // x rounded to tf32
__device__ float g_wq[QKVN * BDIM];              // qkv_w rounded
__device__ float g_wp[BDIM * BDIM];              // proj_w rounded
__device__ float g_bias[NMASK * HEADS * NN];     // mask + rel bias, 7.4 MB

__device__ __forceinline__ uint32_t cvt_tf32(float x) {
    uint32_t r;
    asm("cvt.rna.tf32.f32 %0, %1;" : "=r"(r) : "f"(x));
    return r;
}
__device__ __forceinline__ float round_tf32f(float x) {
    return __uint_as_float(cvt_tf32(x));
}
__device__ __forceinline__ uint32_t smem_u32(const void* p) {
    uint32_t r;
    asm("{ .reg .u64 t; cvta.to.shared.u64 t, %1; cvt.u32.u64 %0, t; }"
        : "=r"(r) : "l"(p));
    return r;
}
#define CP_ASYNC16(dst_u32, src_ptr) \
    asm volatile("cp.async.cg.shared.global [%0], [%1], 16;" :: "r"(dst_u32), "l"(src_ptr))
#define CP_COMMIT() asm volatile("cp.async.commit_group;" ::: "memory")
#define CP_WAIT1()  asm volatile("cp.async.wait_group 1;" ::: "memory")

// ---------------------------------------------------------------------------
// Prep kernels
// ---------------------------------------------------------------------------
__global__ void round_tf32_kernel(const float* __restrict__ src,
                                  float* __restrict__ dst, int n4) {
    int i = blockIdx.x * blockDim.x + threadIdx.x;
    if (i < n4) {
        float4 v = ((const float4*)src)[i];
        v.x = round_tf32f(v.x); v.y = round_tf32f(v.y);
        v.z = round_tf32f(v.z); v.w = round_tf32f(v.w);
        ((float4*)dst)[i] = v;
    }
}

// combined[w][h][e] = mask[w][e] + rel_table[rel_index[e]*HEADS + h]
__global__ void bias_prep_kernel(const float* __restrict__ mask,
                                 const float* __restrict__ rel_table,
                                 const int*   __restrict__ rel_index) {
    int idx = blockIdx.x * blockDim.x + threadIdx.x;
    const int total = NMASK * HEADS * NN;
    if (idx < total) {
        int e  = idx % NN;
        int wh = idx / NN;
        int h  = wh % HEADS;
        int w  = wh / HEADS;
        g_bias[idx] = mask[w * NN + e] + rel_table[rel_index[e] * HEADS + h];
    }
}

// ---------------------------------------------------------------------------
// TF32 GEMM (inputs pre-rounded): C[m][n]=sum_k A[m][k]*W[n][k]+bias[n]
// 128x128x16 CTA tile, 8 warps (4x2) of 32x64, 2-stage cp.async, static smem.
// ---------------------------------------------------------------------------
__global__ __launch_bounds__(256, 2)
void tf32_gemm_abT_bias(const float* __restrict__ A,
                        const float* __restrict__ W,
                        const float* __restrict__ bias,
                        float* __restrict__ C,
                        int M, int N, int K) {
    constexpr int BM = 128, BN = 128, BK = 16, LD = 20;
    __shared__ float As[2][BM][LD];
    __shared__ float Bs[2][BN][LD];

    const int tid = threadIdx.x;
    const int bm = blockIdx.y * BM;
    const int bn = blockIdx.x * BN;
    const int lane = tid & 31;
    const int warp = tid >> 5;
    const int wm = (warp >> 1) * 32;   // 0,32,64,96
    const int wn = (warp & 1) * 64;    // 0,64
    const int g   = lane >> 2;         // 0..7
    const int tig = lane & 3;          // 0..3

    float acc[2][8][4];
#pragma unroll
    for (int mt = 0; mt < 2; mt++)
#pragma unroll
        for (int nt = 0; nt < 8; nt++)
#pragma unroll
            for (int e = 0; e < 4; e++) acc[mt][nt][e] = 0.0f;

    const int KT = K / BK;

    auto load_stage = [&](int st, int kt) {
        const int k0 = kt * BK;
#pragma unroll
        for (int i = 0; i < 2; i++) {
            int c = tid + i * 256;       // 0..511
            int r = c >> 2;              // 0..127
            int s4 = (c & 3) * 4;
            CP_ASYNC16(smem_u32(&As[st][r][s4]),
                       A + (size_t)(bm + r) * K + k0 + s4);
            CP_ASYNC16(smem_u32(&Bs[st][r][s4]),
                       W + (size_t)(bn + r) * K + k0 + s4);
        }
    };

    auto compute = [&](int st) {
#pragma unroll
        for (int ks = 0; ks < 2; ks++) {
            const int kk = ks * 8 + tig;
            uint32_t a[2][4], bf[8][2];
#pragma unroll
            for (int mt = 0; mt < 2; mt++) {
                int r0 = wm + mt * 16 + g;
                a[mt][0] = __float_as_uint(As[st][r0][kk]);
                a[mt][1] = __float_as_uint(As[st][r0 + 8][kk]);
                a[mt][2] = __float_as_uint(As[st][r0][kk + 4]);
                a[mt][3] = __float_as_uint(As[st][r0 + 8][kk + 4]);
            }
#pragma unroll
            for (int nt = 0; nt < 8; nt++) {
                int c0 = wn + nt * 8 + g;
                bf[nt][0] = __float_as_uint(Bs[st][c0][kk]);
                bf[nt][1] = __float_as_uint(Bs[st][c0][kk + 4]);
            }
#pragma unroll
            for (int mt = 0; mt < 2; mt++)
#pragma unroll
                for (int nt = 0; nt < 8; nt++) {
                    float* c = acc[mt][nt];
                    asm volatile(
                        "mma.sync.aligned.m16n8k8.row.col.f32.tf32.tf32.f32 "
                        "{%0,%1,%2,%3}, {%4,%5,%6,%7}, {%8,%9}, {%0,%1,%2,%3};"
                        : "+f"(c[0]), "+f"(c[1]), "+f"(c[2]), "+f"(c[3])
                        : "r"(a[mt][0]), "r"(a[mt][1]), "r"(a[mt][2]), "r"(a[mt][3]),
                          "r"(bf[nt][0]), "r"(bf[nt][1]));
                }
        }
    };

    load_stage(0, 0);
    CP_COMMIT();

    for (int kt = 0; kt < KT; kt++) {
        if (kt + 1 < KT) load_stage((kt + 1) & 1, kt + 1);
        CP_COMMIT();
        CP_WAIT1();
        __syncthreads();
        compute(kt & 1);
        __syncthreads();
    }

#pragma unroll
    for (int mt = 0; mt < 2; mt++) {
#pragma unroll
        for (int nt = 0; nt < 8; nt++) {
            int row = bm + wm + mt * 16 + g;
            int col = bn + wn + nt * 8 + 2 * tig;
            float b0 = bias[col], b1 = bias[col + 1];
            float2 o0 = {acc[mt][nt][0] + b0, acc[mt][nt][1] + b1};
            float2 o1 = {acc[mt][nt][2] + b0, acc[mt][nt][3] + b1};
            *(float2*)(C + (size_t)row * N + col) = o0;
            *(float2*)(C + (size_t)(row + 8) * N + col) = o1;
        }
    }
}

// ---------------------------------------------------------------------------
// Fused attention per (window, head): 4x4 register tiles, float4 gmem loads,
// combined bias+mask from precomputed table. Output tf32-rounded.
// ---------------------------------------------------------------------------
__global__ __launch_bounds__(128)
void attn_kernel() {
    const int b = blockIdx.x;   // window
    const int h = blockIdx.y;   // head

    __shared__ float qt[HD][52];      // [d][i]
    __shared__ float ktr[HD][52];     // [d][j]
    __shared__ float vsm[52][HD];     // [j][d]
    __shared__ float s[52 * 53];

    const int tid = threadIdx.x;
    const float scale = 0.17677669529663687f;  // 32^-0.5

    // float4 loads: 49 tokens x 8 float4 per matrix
    const float* base = g_qkv + (size_t)b * NTOK * QKVN + h * HD;
    for (int e = tid; e < NTOK * 8; e += 128) {
        int i = e >> 3, d4 = (e & 7) * 4;
        const float* p = base + i * QKVN + d4;
        float4 qv = *(const float4*)(p);
        float4 kv = *(const float4*)(p + BDIM);
        float4 vv = *(const float4*)(p + 2 * BDIM);
        qt[d4 + 0][i] = qv.x; qt[d4 + 1][i] = qv.y;
        qt[d4 + 2][i] = qv.z; qt[d4 + 3][i] = qv.w;
        ktr[d4 + 0][i] = kv.x; ktr[d4 + 1][i] = kv.y;
        ktr[d4 + 2][i] = kv.z; ktr[d4 + 3][i] = kv.w;
        *(float4*)&vsm[i][d4] = vv;
    }
    __syncthreads();

    // Scores: 13x13 grid of 4x4 tiles.
    const float* cb = g_bias +
        ((size_t)(b & (NMASK - 1)) * HEADS + h) * NN;
    for (int tt = tid; tt < 169; tt += 128) {
        int ig = tt / 13, jg = tt - ig * 13;
        int i0 = ig * 4, j0 = jg * 4;
        float acc[4][4];
#pragma unroll
        for (int r = 0; r < 4; r++)
#pragma unroll
            for (int c = 0; c < 4; c++) acc[r][c] = 0.0f;

#pragma unroll 8
        for (int d = 0; d < HD; d++) {
            float qv[4], kv[4];
            *(float4*)qv = *(const float4*)&qt[d][i0];
            *(float4*)kv = *(const float4*)&ktr[d][j0];
#pragma unroll
            for (int r = 0; r < 4; r++)
#pragma unroll
                for (int c = 0; c < 4; c++)
                    acc[r][c] = fmaf(qv[r], kv[c], acc[r][c]);
        }
#pragma unroll
        for (int r = 0; r < 4; r++) {
            int i = i0 + r;
            if (i >= NTOK) continue;
#pragma unroll
            for (int c = 0; c < 4; c++) {
                int j = j0 + c;
                if (j >= NTOK) continue;
                s[i * 53 + j] = fmaf(acc[r][c], scale, cb[i * NTOK + j]);
            }
        }
    }
    __syncthreads();

    // Softmax: 2 lanes per row, shfl combine.
    {
        int i = tid >> 1, half = tid & 1;
        bool act = (i < NTOK);
        int j0 = half * 25;
        int cnt = act ? (half ? 24 : 25) : 0;
        float m = -1e30f;
        for (int jj = 0; jj < cnt; jj++) m = fmaxf(m, s[i * 53 + j0 + jj]);
        m = fmaxf(m, __shfl_xor_sync(0xffffffffu, m, 1));
        float sum = 0.0f;
        for (int jj = 0; jj < cnt; jj++) {
            float e = __expf(s[i * 53 + j0 + jj] - m);
            s[i * 53 + j0 + jj] = e;
            sum += e;
        }
        sum += __shfl_xor_sync(0xffffffffu, sum, 1);
        float inv = 1.0f / sum;
        for (int jj = 0; jj < cnt; jj++) s[i * 53 + j0 + jj] *= inv;
    }
    __syncthreads();

    // PV: 13x8 grid of 4x4 tiles; one tile per thread (tid<104).
    if (tid < 104) {
        int ig = tid >> 3, dg = tid & 7;
        int i0 = ig * 4, d0 = dg * 4;
        float acc[4][4];
#pragma unroll
        for (int r = 0; r < 4; r++)
#pragma unroll
            for (int c = 0; c < 4; c++) acc[r][c] = 0.0f;

#pragma unroll 7
        for (int j = 0; j < NTOK; j++) {
            float sv[4];
#pragma unroll
            for (int r = 0; r < 4; r++) sv[r] = s[(i0 + r) * 53 + j];
            float vv[4];
            *(float4*)vv = *(const float4*)&vsm[j][d0];
#pragma unroll
            for (int r = 0; r < 4; r++)
#pragma unroll
                for (int c = 0; c < 4; c++)
                    acc[r][c] = fmaf(sv[r], vv[c], acc[r][c]);
        }
        float* outb = g_attn + (size_t)b * NTOK * BDIM + h * HD + d0;
#pragma unroll
        for (int r = 0; r < 4; r++) {
            int i = i0 + r;
            if (i < NTOK) {
                float4 o = {round_tf32f(acc[r][0]), round_tf32f(acc[r][1]),
                            round_tf32f(acc[r][2]), round_tf32f(acc[r][3])};
                *(float4*)(outb + (size_t)i * BDIM) = o;
            }
        }
    }
}

// ---------------------------------------------------------------------------
extern "C" void kernel_launch(void* const* d_in, const int* in_sizes, int n_in,
                              void* d_out, int out_size) {
    const float* x         = (const float*)d_in[0];  // [2048, 49, 384]
    const float* mask      = (const float*)d_in[1];  // [64, 49, 49]
    const float* qkv_w     = (const float*)d_in[2];  // [1152, 384]
    const float* qkv_b     = (const float*)d_in[3];  // [1152]
    const float* proj_w    = (const float*)d_in[4];  // [384, 384]
    const float* proj_b    = (const float*)d_in[5];  // [384]
    const float* rel_table = (const float*)d_in[6];  // [169, 12]
    const int*   rel_index = (const int*)d_in[7];    // [49, 49]
    float* out = (float*)d_out;                      // [2048, 49, 384]

    float *qkv_buf, *attn_buf, *xr, *wq, *wp;
    cudaGetSymbolAddress((void**)&qkv_buf, g_qkv);
    cudaGetSymbolAddress((void**)&attn_buf, g_attn);
    cudaGetSymbolAddress((void**)&xr, g_xr);
    cudaGetSymbolAddress((void**)&wq, g_wq);
    cudaGetSymbolAddress((void**)&wp, g_wp);

    // 0) Prep: tf32-round GEMM inputs; build combined bias+mask table.
    {
        int n4 = (MROWS * BDIM) / 4;
        round_tf32_kernel<<<(n4 + 255) / 256, 256>>>(x, xr, n4);
        int w4 = (QKVN * BDIM) / 4;
        round_tf32_kernel<<<(w4 + 255) / 256, 256>>>(qkv_w, wq, w4);
        int p4 = (BDIM * BDIM) / 4;
        round_tf32_kernel<<<(p4 + 255) / 256, 256>>>(proj_w, wp, p4);
        int bt = NMASK * HEADS * NN;
        bias_prep_kernel<<<(bt + 255) / 256, 256>>>(mask, rel_table, rel_index);
    }

    // 1) QKV GEMM: [100352, 384] @ [1152, 384]^T -> [100352, 1152]
    {
        dim3 grid(QKVN / 128, MROWS / 128);   // (9, 784)
        tf32_gemm_abT_bias<<<grid, 256>>>(xr, wq, qkv_b, qkv_buf,
                                          MROWS, QKVN, BDIM);
    }

    // 2) attention per (window, head)
    {
        dim3 grid(NWIN, HEADS);               // (2048, 12)
        attn_kernel<<<grid, 128>>>();
    }

    // 3) proj GEMM: [100352, 384] @ [384, 384]^T -> [100352, 384]
    {
        dim3 grid(BDIM / 128, MROWS / 128);   // (3, 784)
        tf32_gemm_abT_bias<<<grid, 256>>>(attn_buf, wp, proj_b, out,
                                          MROWS, BDIM, BDIM);
    }
}

// round 9
// speedup vs baseline: 1.9245x; 1.8151x over previous
#include <cuda_runtime.h>
#include <cuda_bf16.h>
#include <cstdint>

// ---------------------------------------------------------------------------
// WindowAttention (Swin): B=2048 windows, N=49 tokens, DIM=384, HEADS=12, hd=32
// R9: Attention rewritten on tensor cores (mma.sync m16n8k8 tf32):
//     pad 49->64, warp-private 16-row strips, register softmax, P via smem.
//     GEMMs + prep unchanged from R8.
// ---------------------------------------------------------------------------

#define BDIM   384
#define HEADS  12
#define HD     32
#define NTOK   49
#define NWIN   2048
#define NMASK  64
#define MROWS  (NWIN * NTOK)        // 100352
#define QKVN   (3 * BDIM)           // 1152
#define NN     (NTOK * NTOK)        // 2401

__device__ float g_qkv[(size_t)MROWS * QKVN];    // ~462 MB
__device__ float g_attn[(size_t)MROWS * BDIM];   // ~154 MB (tf32-rounded)
__device__ float g_xr[(size_t)MROWS * BDIM];     // x rounded to tf32
__device__ float g_wq[QKVN * BDIM];              // qkv_w rounded
__device__ float g_wp[BDIM * BDIM];              // proj_w rounded
__device__ float g_bias[NMASK * HEADS * NN];     // mask + rel bias, 7.4 MB

__device__ __forceinline__ uint32_t cvt_tf32(float x) {
    uint32_t r;
    asm("cvt.rna.tf32.f32 %0, %1;" : "=r"(r) : "f"(x));
    return r;
}
__device__ __forceinline__ float round_tf32f(float x) {
    return __uint_as_float(cvt_tf32(x));
}
__device__ __forceinline__ uint32_t smem_u32(const void* p) {
    uint32_t r;
    asm("{ .reg .u64 t; cvta.to.shared.u64 t, %1; cvt.u32.u64 %0, t; }"
        : "=r"(r) : "l"(p));
    return r;
}
__device__ __forceinline__ void mma_tf32(float* c, const uint32_t* a,
                                         uint32_t b0, uint32_t b1) {
    asm volatile(
        "mma.sync.aligned.m16n8k8.row.col.f32.tf32.tf32.f32 "
        "{%0,%1,%2,%3}, {%4,%5,%6,%7}, {%8,%9}, {%0,%1,%2,%3};"
        : "+f"(c[0]), "+f"(c[1]), "+f"(c[2]), "+f"(c[3])
        : "r"(a[0]), "r"(a[1]), "r"(a[2]), "r"(a[3]), "r"(b0), "r"(b1));
}
#define CP_ASYNC16(dst_u32, src_ptr) \
    asm volatile("cp.async.cg.shared.global [%0], [%1], 16;" :: "r"(dst_u32), "l"(src_ptr))
#define CP_COMMIT() asm volatile("cp.async.commit_group;" ::: "memory")
#define CP_WAIT1()  asm volatile("cp.async.wait_group 1;" ::: "memory")

// ---------------------------------------------------------------------------
// Prep kernels
// ---------------------------------------------------------------------------
__global__ void round_tf32_kernel(const float* __restrict__ src,
                                  float* __restrict__ dst, int n4) {
    int i = blockIdx.x * blockDim.x + threadIdx.x;
    if (i < n4) {
        float4 v = ((const float4*)src)[i];
        v.x = round_tf32f(v.x); v.y = round_tf32f(v.y);
        v.z = round_tf32f(v.z); v.w = round_tf32f(v.w);
        ((float4*)dst)[i] = v;
    }
}

__global__ void bias_prep_kernel(const float* __restrict__ mask,
                                 const float* __restrict__ rel_table,
                                 const int*   __restrict__ rel_index) {
    int idx = blockIdx.x * blockDim.x + threadIdx.x;
    const int total = NMASK * HEADS * NN;
    if (idx < total) {
        int e  = idx % NN;
        int wh = idx / NN;
        int h  = wh % HEADS;
        int w  = wh / HEADS;
        g_bias[idx] = mask[w * NN + e] + rel_table[rel_index[e] * HEADS + h];
    }
}

// ---------------------------------------------------------------------------
// TF32 GEMM (inputs pre-rounded): C[m][n]=sum_k A[m][k]*W[n][k]+bias[n]
// 128x128x16 CTA tile, 8 warps (4x2) of 32x64, 2-stage cp.async, static smem.
// ---------------------------------------------------------------------------
__global__ __launch_bounds__(256, 2)
void tf32_gemm_abT_bias(const float* __restrict__ A,
                        const float* __restrict__ W,
                        const float* __restrict__ bias,
                        float* __restrict__ C,
                        int M, int N, int K) {
    constexpr int BM = 128, BN = 128, BK = 16, LD = 20;
    __shared__ float As[2][BM][LD];
    __shared__ float Bs[2][BN][LD];

    const int tid = threadIdx.x;
    const int bm = blockIdx.y * BM;
    const int bn = blockIdx.x * BN;
    const int lane = tid & 31;
    const int warp = tid >> 5;
    const int wm = (warp >> 1) * 32;
    const int wn = (warp & 1) * 64;
    const int g   = lane >> 2;
    const int tig = lane & 3;

    float acc[2][8][4];
#pragma unroll
    for (int mt = 0; mt < 2; mt++)
#pragma unroll
        for (int nt = 0; nt < 8; nt++)
#pragma unroll
            for (int e = 0; e < 4; e++) acc[mt][nt][e] = 0.0f;

    const int KT = K / BK;

    auto load_stage = [&](int st, int kt) {
        const int k0 = kt * BK;
#pragma unroll
        for (int i = 0; i < 2; i++) {
            int c = tid + i * 256;
            int r = c >> 2;
            int s4 = (c & 3) * 4;
            CP_ASYNC16(smem_u32(&As[st][r][s4]),
                       A + (size_t)(bm + r) * K + k0 + s4);
            CP_ASYNC16(smem_u32(&Bs[st][r][s4]),
                       W + (size_t)(bn + r) * K + k0 + s4);
        }
    };

    auto compute = [&](int st) {
#pragma unroll
        for (int ks = 0; ks < 2; ks++) {
            const int kk = ks * 8 + tig;
            uint32_t a[2][4], bf[8][2];
#pragma unroll
            for (int mt = 0; mt < 2; mt++) {
                int r0 = wm + mt * 16 + g;
                a[mt][0] = __float_as_uint(As[st][r0][kk]);
                a[mt][1] = __float_as_uint(As[st][r0 + 8][kk]);
                a[mt][2] = __float_as_uint(As[st][r0][kk + 4]);
                a[mt][3] = __float_as_uint(As[st][r0 + 8][kk + 4]);
            }
#pragma unroll
            for (int nt = 0; nt < 8; nt++) {
                int c0 = wn + nt * 8 + g;
                bf[nt][0] = __float_as_uint(Bs[st][c0][kk]);
                bf[nt][1] = __float_as_uint(Bs[st][c0][kk + 4]);
            }
#pragma unroll
            for (int mt = 0; mt < 2; mt++)
#pragma unroll
                for (int nt = 0; nt < 8; nt++)
                    mma_tf32(acc[mt][nt], a[mt], bf[nt][0], bf[nt][1]);
        }
    };

    load_stage(0, 0);
    CP_COMMIT();

    for (int kt = 0; kt < KT; kt++) {
        if (kt + 1 < KT) load_stage((kt + 1) & 1, kt + 1);
        CP_COMMIT();
        CP_WAIT1();
        __syncthreads();
        compute(kt & 1);
        __syncthreads();
    }

#pragma unroll
    for (int mt = 0; mt < 2; mt++) {
#pragma unroll
        for (int nt = 0; nt < 8; nt++) {
            int row = bm + wm + mt * 16 + g;
            int col = bn + wn + nt * 8 + 2 * tig;
            float b0 = bias[col], b1 = bias[col + 1];
            float2 o0 = {acc[mt][nt][0] + b0, acc[mt][nt][1] + b1};
            float2 o1 = {acc[mt][nt][2] + b0, acc[mt][nt][3] + b1};
            *(float2*)(C + (size_t)row * N + col) = o0;
            *(float2*)(C + (size_t)(row + 8) * N + col) = o1;
        }
    }
}

// ---------------------------------------------------------------------------
// Tensor-core attention per (window, head). 128 threads = 4 warps.
// Warp w owns rows [16w, 16w+16). Pad 49 -> 64 everywhere.
//   S = scale*(Q K^T) + bias+mask (tf32 mma, K=32)
//   softmax in registers (quad shfl)
//   O = P V (tf32 mma, K=64), P staged via per-warp smem strip.
// ---------------------------------------------------------------------------
__global__ __launch_bounds__(128)
void attn_mma_kernel() {
    const int b = blockIdx.x;
    const int h = blockIdx.y;

    __shared__ float qsm[64][36];
    __shared__ float ksm[64][36];
    __shared__ float vsm[64][36];
    __shared__ float ps[4][16][68];

    const int tid = threadIdx.x;
    const int lane = tid & 31;
    const int w = tid >> 5;
    const int g = lane >> 2;          // 0..7
    const int tig = lane & 3;         // 0..3
    const int m0 = w * 16;
    const float scale = 0.17677669529663687f;  // 32^-0.5

    // Zero pad rows 49..63 (prevent NaN propagation through mma).
    for (int e = tid; e < (64 - NTOK) * 9; e += 128) {
        int i = NTOK + e / 9, c4 = (e % 9) * 4;
        float4 z = {0.f, 0.f, 0.f, 0.f};
        *(float4*)&qsm[i][c4] = z;
        *(float4*)&ksm[i][c4] = z;
        *(float4*)&vsm[i][c4] = z;
    }
    // Load q,k,v (float4).
    const float* base = g_qkv + (size_t)b * NTOK * QKVN + h * HD;
    for (int e = tid; e < NTOK * 8; e += 128) {
        int i = e >> 3, d4 = (e & 7) * 4;
        const float* p = base + i * QKVN + d4;
        *(float4*)&qsm[i][d4] = *(const float4*)p;
        *(float4*)&ksm[i][d4] = *(const float4*)(p + BDIM);
        *(float4*)&vsm[i][d4] = *(const float4*)(p + 2 * BDIM);
    }
    __syncthreads();

    // ---- Scores: S[16][64] per warp, K = 32 ----
    float acc[8][4];
#pragma unroll
    for (int nt = 0; nt < 8; nt++)
#pragma unroll
        for (int e = 0; e < 4; e++) acc[nt][e] = 0.0f;

#pragma unroll
    for (int k0 = 0; k0 < HD; k0 += 8) {
        uint32_t a[4];
        a[0] = cvt_tf32(qsm[m0 + g][k0 + tig]);
        a[1] = cvt_tf32(qsm[m0 + g + 8][k0 + tig]);
        a[2] = cvt_tf32(qsm[m0 + g][k0 + tig + 4]);
        a[3] = cvt_tf32(qsm[m0 + g + 8][k0 + tig + 4]);
#pragma unroll
        for (int nt = 0; nt < 8; nt++) {
            uint32_t b0 = cvt_tf32(ksm[nt * 8 + g][k0 + tig]);
            uint32_t b1 = cvt_tf32(ksm[nt * 8 + g][k0 + tig + 4]);
            mma_tf32(acc[nt], a, b0, b1);
        }
    }

    // ---- bias + mask + padding guards; row stats ----
    const float* cb = g_bias + ((size_t)(b & (NMASK - 1)) * HEADS + h) * NN;
    const int r0 = m0 + g, r1 = m0 + g + 8;
    float m0v = -1e30f, m1v = -1e30f;
#pragma unroll
    for (int nt = 0; nt < 8; nt++) {
        int j = nt * 8 + 2 * tig;
        float b00 = (r0 < NTOK && j < NTOK)     ? cb[r0 * NTOK + j]     : -1e30f;
        float b01 = (r0 < NTOK && j + 1 < NTOK) ? cb[r0 * NTOK + j + 1] : -1e30f;
        float b10 = (r1 < NTOK && j < NTOK)     ? cb[r1 * NTOK + j]     : -1e30f;
        float b11 = (r1 < NTOK && j + 1 < NTOK) ? cb[r1 * NTOK + j + 1] : -1e30f;
        acc[nt][0] = fmaf(acc[nt][0], scale, b00);
        acc[nt][1] = fmaf(acc[nt][1], scale, b01);
        acc[nt][2] = fmaf(acc[nt][2], scale, b10);
        acc[nt][3] = fmaf(acc[nt][3], scale, b11);
        m0v = fmaxf(m0v, fmaxf(acc[nt][0], acc[nt][1]));
        m1v = fmaxf(m1v, fmaxf(acc[nt][2], acc[nt][3]));
    }
    m0v = fmaxf(m0v, __shfl_xor_sync(0xffffffffu, m0v, 1));
    m0v = fmaxf(m0v, __shfl_xor_sync(0xffffffffu, m0v, 2));
    m1v = fmaxf(m1v, __shfl_xor_sync(0xffffffffu, m1v, 1));
    m1v = fmaxf(m1v, __shfl_xor_sync(0xffffffffu, m1v, 2));

    float s0 = 0.f, s1 = 0.f;
#pragma unroll
    for (int nt = 0; nt < 8; nt++) {
        acc[nt][0] = __expf(acc[nt][0] - m0v);
        acc[nt][1] = __expf(acc[nt][1] - m0v);
        acc[nt][2] = __expf(acc[nt][2] - m1v);
        acc[nt][3] = __expf(acc[nt][3] - m1v);
        s0 += acc[nt][0] + acc[nt][1];
        s1 += acc[nt][2] + acc[nt][3];
    }
    s0 += __shfl_xor_sync(0xffffffffu, s0, 1);
    s0 += __shfl_xor_sync(0xffffffffu, s0, 2);
    s1 += __shfl_xor_sync(0xffffffffu, s1, 1);
    s1 += __shfl_xor_sync(0xffffffffu, s1, 2);
    const float inv0 = 1.0f / s0, inv1 = 1.0f / s1;

    // Store P (tf32-rounded) into the warp-private strip.
#pragma unroll
    for (int nt = 0; nt < 8; nt++) {
        int j = nt * 8 + 2 * tig;
        float2 p0 = {round_tf32f(acc[nt][0] * inv0), round_tf32f(acc[nt][1] * inv0)};
        float2 p1 = {round_tf32f(acc[nt][2] * inv1), round_tf32f(acc[nt][3] * inv1)};
        *(float2*)&ps[w][g][j]     = p0;
        *(float2*)&ps[w][g + 8][j] = p1;
    }
    __syncwarp();

    // ---- PV: O[16][32] per warp, K = 64 ----
    float out[4][4];
#pragma unroll
    for (int nt = 0; nt < 4; nt++)
#pragma unroll
        for (int e = 0; e < 4; e++) out[nt][e] = 0.0f;

#pragma unroll
    for (int k0 = 0; k0 < 64; k0 += 8) {
        uint32_t a[4];
        a[0] = __float_as_uint(ps[w][g][k0 + tig]);
        a[1] = __float_as_uint(ps[w][g + 8][k0 + tig]);
        a[2] = __float_as_uint(ps[w][g][k0 + tig + 4]);
        a[3] = __float_as_uint(ps[w][g + 8][k0 + tig + 4]);
#pragma unroll
        for (int nt = 0; nt < 4; nt++) {
            uint32_t b0 = cvt_tf32(vsm[k0 + tig][nt * 8 + g]);
            uint32_t b1 = cvt_tf32(vsm[k0 + tig + 4][nt * 8 + g]);
            mma_tf32(out[nt], a, b0, b1);
        }
    }

    // ---- store (tf32-rounded, feeds proj GEMM) ----
    float* outb = g_attn + (size_t)b * NTOK * BDIM + h * HD;
#pragma unroll
    for (int nt = 0; nt < 4; nt++) {
        int d0 = nt * 8 + 2 * tig;
        if (r0 < NTOK) {
            float2 o = {round_tf32f(out[nt][0]), round_tf32f(out[nt][1])};
            *(float2*)(outb + (size_t)r0 * BDIM + d0) = o;
        }
        if (r1 < NTOK) {
            float2 o = {round_tf32f(out[nt][2]), round_tf32f(out[nt][3])};
            *(float2*)(outb + (size_t)r1 * BDIM + d0) = o;
        }
    }
}

// ---------------------------------------------------------------------------
extern "C" void kernel_launch(void* const* d_in, const int* in_sizes, int n_in,
                              void* d_out, int out_size) {
    const float* x         = (const float*)d_in[0];  // [2048, 49, 384]
    const float* mask      = (const float*)d_in[1];  // [64, 49, 49]
    const float* qkv_w     = (const float*)d_in[2];  // [1152, 384]
    const float* qkv_b     = (const float*)d_in[3];  // [1152]
    const float* proj_w    = (const float*)d_in[4];  // [384, 384]
    const float* proj_b    = (const float*)d_in[5];  // [384]
    const float* rel_table = (const float*)d_in[6];  // [169, 12]
    const int*   rel_index = (const int*)d_in[7];    // [49, 49]
    float* out = (float*)d_out;                      // [2048, 49, 384]

    float *qkv_buf, *attn_buf, *xr, *wq, *wp;
    cudaGetSymbolAddress((void**)&qkv_buf, g_qkv);
    cudaGetSymbolAddress((void**)&attn_buf, g_attn);
    cudaGetSymbolAddress((void**)&xr, g_xr);
    cudaGetSymbolAddress((void**)&wq, g_wq);
    cudaGetSymbolAddress((void**)&wp, g_wp);

    // 0) Prep: tf32-round GEMM inputs; build combined bias+mask table.
    {
        int n4 = (MROWS * BDIM) / 4;
        round_tf32_kernel<<<(n4 + 255) / 256, 256>>>(x, xr, n4);
        int w4 = (QKVN * BDIM) / 4;
        round_tf32_kernel<<<(w4 + 255) / 256, 256>>>(qkv_w, wq, w4);
        int p4 = (BDIM * BDIM) / 4;
        round_tf32_kernel<<<(p4 + 255) / 256, 256>>>(proj_w, wp, p4);
        int bt = NMASK * HEADS * NN;
        bias_prep_kernel<<<(bt + 255) / 256, 256>>>(mask, rel_table, rel_index);
    }

    // 1) QKV GEMM: [100352, 384] @ [1152, 384]^T -> [100352, 1152]
    {
        dim3 grid(QKVN / 128, MROWS / 128);   // (9, 784)
        tf32_gemm_abT_bias<<<grid, 256>>>(xr, wq, qkv_b, qkv_buf,
                                          MROWS, QKVN, BDIM);
    }

    // 2) attention per (window, head), tensor-core path
    {
        dim3 grid(NWIN, HEADS);               // (2048, 12)
        attn_mma_kernel<<<grid, 128>>>();
    }

    // 3) proj GEMM: [100352, 384] @ [384, 384]^T -> [100352, 384]
    {
        dim3 grid(BDIM / 128, MROWS / 128);   // (3, 784)
        tf32_gemm_abT_bias<<<grid, 256>>>(attn_buf, wp, proj_b, out,
                                          MROWS, BDIM, BDIM);
    }
}

// round 13
// speedup vs baseline: 2.1880x; 1.1369x over previous
#include <cuda_runtime.h>
#include <cuda_bf16.h>
#include <cstdint>

// ---------------------------------------------------------------------------
// WindowAttention (Swin): B=2048 windows, N=49 tokens, DIM=384, HEADS=12, hd=32
// R10: GEMM -> 3-stage cp.async, ONE __syncthreads per k-tile, in-loop cvt of
//      A fragments (x rounding pass eliminated). Attention: R9 tensor-core
//      kernel (epilogue rounding dropped; proj GEMM cvts A in-loop).
// ---------------------------------------------------------------------------

#define BDIM   384
#define HEADS  12
#define HD     32
#define NTOK   49
#define NWIN   2048
#define NMASK  64
#define MROWS  (NWIN * NTOK)        // 100352
#define QKVN   (3 * BDIM)           // 1152
#define NN     (NTOK * NTOK)        // 2401

__device__ float g_qkv[(size_t)MROWS * QKVN];    // ~462 MB
__device__ float g_attn[(size_t)MROWS * BDIM];   // ~154 MB
__device__ float g_wq[QKVN * BDIM];              // qkv_w rounded
__device__ float g_wp[BDIM * BDIM];              // proj_w rounded
__device__ float g_bias[NMASK * HEADS * NN];     // mask + rel bias, 7.4 MB

__device__ __forceinline__ uint32_t cvt_tf32(float x) {
    uint32_t r;
    asm("cvt.rna.tf32.f32 %0, %1;" : "=r"(r) : "f"(x));
    return r;
}
__device__ __forceinline__ float round_tf32f(float x) {
    return __uint_as_float(cvt_tf32(x));
}
__device__ __forceinline__ uint32_t smem_u32(const void* p) {
    uint32_t r;
    asm("{ .reg .u64 t; cvta.to.shared.u64 t, %1; cvt.u32.u64 %0, t; }"
        : "=r"(r) : "l"(p));
    return r;
}
__device__ __forceinline__ void mma_tf32(float* c, const uint32_t* a,
                                         uint32_t b0, uint32_t b1) {
    asm volatile(
        "mma.sync.aligned.m16n8k8.row.col.f32.tf32.tf32.f32 "
        "{%0,%1,%2,%3}, {%4,%5,%6,%7}, {%8,%9}, {%0,%1,%2,%3};"
        : "+f"(c[0]), "+f"(c[1]), "+f"(c[2]), "+f"(c[3])
        : "r"(a[0]), "r"(a[1]), "r"(a[2]), "r"(a[3]), "r"(b0), "r"(b1));
}
#define CP_ASYNC16(dst_u32, src_ptr) \
    asm volatile("cp.async.cg.shared.global [%0], [%1], 16;" :: "r"(dst_u32), "l"(src_ptr))
#define CP_COMMIT() asm volatile("cp.async.commit_group;" ::: "memory")
#define CP_WAIT_G1() asm volatile("cp.async.wait_group 1;" ::: "memory")

// ---------------------------------------------------------------------------
// Prep kernels
// ---------------------------------------------------------------------------
__global__ void round_tf32_kernel(const float* __restrict__ src,
                                  float* __restrict__ dst, int n4) {
    int i = blockIdx.x * blockDim.x + threadIdx.x;
    if (i < n4) {
        float4 v = ((const float4*)src)[i];
        v.x = round_tf32f(v.x); v.y = round_tf32f(v.y);
        v.z = round_tf32f(v.z); v.w = round_tf32f(v.w);
        ((float4*)dst)[i] = v;
    }
}

__global__ void bias_prep_kernel(const float* __restrict__ mask,
                                 const float* __restrict__ rel_table,
                                 const int*   __restrict__ rel_index) {
    int idx = blockIdx.x * blockDim.x + threadIdx.x;
    const int total = NMASK * HEADS * NN;
    if (idx < total) {
        int e  = idx % NN;
        int wh = idx / NN;
        int h  = wh % HEADS;
        int w  = wh / HEADS;
        g_bias[idx] = mask[w * NN + e] + rel_table[rel_index[e] * HEADS + h];
    }
}

// ---------------------------------------------------------------------------
// TF32 GEMM: C[m][n]=sum_k tf32(A[m][k])*W[n][k]+bias[n]
// A raw fp32 (cvt'd at fragment load), W pre-rounded tf32.
// 128x128x16 CTA tile, 8 warps (4x2) of 32x64, 3-stage cp.async,
// ONE __syncthreads per k-tile. Dynamic smem 61440 B, 2 CTA/SM.
// ---------------------------------------------------------------------------
__global__ __launch_bounds__(256, 2)
void tf32_gemm_abT_bias(const float* __restrict__ A,
                        const float* __restrict__ W,
                        const float* __restrict__ bias,
                        float* __restrict__ C,
                        int M, int N, int K) {
    constexpr int BM = 128, BN = 128, BK = 16, LD = 20;
    extern __shared__ float smem[];
    float* As = smem;                   // [3][BM][LD]
    float* Bs = smem + 3 * BM * LD;     // [3][BN][LD]

    const int tid = threadIdx.x;
    const int bm = blockIdx.y * BM;
    const int bn = blockIdx.x * BN;
    const int lane = tid & 31;
    const int warp = tid >> 5;
    const int wm = (warp >> 1) * 32;
    const int wn = (warp & 1) * 64;
    const int g   = lane >> 2;
    const int tig = lane & 3;

    float acc[2][8][4];
#pragma unroll
    for (int mt = 0; mt < 2; mt++)
#pragma unroll
        for (int nt = 0; nt < 8; nt++)
#pragma unroll
            for (int e = 0; e < 4; e++) acc[mt][nt][e] = 0.0f;

    const int KT = K / BK;

    auto load_stage = [&](int st, int kt) {
        const int k0 = kt * BK;
        float* as = As + st * (BM * LD);
        float* bs = Bs + st * (BN * LD);
#pragma unroll
        for (int i = 0; i < 2; i++) {
            int c = tid + i * 256;       // 0..511
            int r = c >> 2;              // 0..127
            int s4 = (c & 3) * 4;
            CP_ASYNC16(smem_u32(&as[r * LD + s4]),
                       A + (size_t)(bm + r) * K + k0 + s4);
            CP_ASYNC16(smem_u32(&bs[r * LD + s4]),
                       W + (size_t)(bn + r) * K + k0 + s4);
        }
    };

    auto compute = [&](int st) {
        const float* as = As + st * (BM * LD);
        const float* bs = Bs + st * (BN * LD);
#pragma unroll
        for (int ks = 0; ks < 2; ks++) {
            const int kk = ks * 8 + tig;
            uint32_t a[2][4], bf[8][2];
#pragma unroll
            for (int mt = 0; mt < 2; mt++) {
                int r0 = wm + mt * 16 + g;
                a[mt][0] = cvt_tf32(as[r0 * LD + kk]);
                a[mt][1] = cvt_tf32(as[(r0 + 8) * LD + kk]);
                a[mt][2] = cvt_tf32(as[r0 * LD + kk + 4]);
                a[mt][3] = cvt_tf32(as[(r0 + 8) * LD + kk + 4]);
            }
#pragma unroll
            for (int nt = 0; nt < 8; nt++) {
                int c0 = wn + nt * 8 + g;
                bf[nt][0] = __float_as_uint(bs[c0 * LD + kk]);
                bf[nt][1] = __float_as_uint(bs[c0 * LD + kk + 4]);
            }
#pragma unroll
            for (int mt = 0; mt < 2; mt++)
#pragma unroll
                for (int nt = 0; nt < 8; nt++)
                    mma_tf32(acc[mt][nt], a[mt], bf[nt][0], bf[nt][1]);
        }
    };

    load_stage(0, 0); CP_COMMIT();
    load_stage(1, 1); CP_COMMIT();

    for (int kt = 0; kt < KT; kt++) {
        CP_WAIT_G1();
        __syncthreads();
        compute(kt % 3);
        if (kt + 2 < KT) load_stage((kt + 2) % 3, kt + 2);
        CP_COMMIT();
    }

#pragma unroll
    for (int mt = 0; mt < 2; mt++) {
#pragma unroll
        for (int nt = 0; nt < 8; nt++) {
            int row = bm + wm + mt * 16 + g;
            int col = bn + wn + nt * 8 + 2 * tig;
            float b0 = bias[col], b1 = bias[col + 1];
            float2 o0 = {acc[mt][nt][0] + b0, acc[mt][nt][1] + b1};
            float2 o1 = {acc[mt][nt][2] + b0, acc[mt][nt][3] + b1};
            *(float2*)(C + (size_t)row * N + col) = o0;
            *(float2*)(C + (size_t)(row + 8) * N + col) = o1;
        }
    }
}

// ---------------------------------------------------------------------------
// Tensor-core attention per (window, head). 128 threads = 4 warps.
// Warp w owns rows [16w, 16w+16). Pad 49 -> 64.
// ---------------------------------------------------------------------------
__global__ __launch_bounds__(128)
void attn_mma_kernel() {
    const int b = blockIdx.x;
    const int h = blockIdx.y;

    __shared__ float qsm[64][36];
    __shared__ float ksm[64][36];
    __shared__ float vsm[64][36];
    __shared__ float ps[4][16][68];

    const int tid = threadIdx.x;
    const int lane = tid & 31;
    const int w = tid >> 5;
    const int g = lane >> 2;          // 0..7
    const int tig = lane & 3;         // 0..3
    const int m0 = w * 16;
    const float scale = 0.17677669529663687f;  // 32^-0.5

    for (int e = tid; e < (64 - NTOK) * 9; e += 128) {
        int i = NTOK + e / 9, c4 = (e % 9) * 4;
        float4 z = {0.f, 0.f, 0.f, 0.f};
        *(float4*)&qsm[i][c4] = z;
        *(float4*)&ksm[i][c4] = z;
        *(float4*)&vsm[i][c4] = z;
    }
    const float* base = g_qkv + (size_t)b * NTOK * QKVN + h * HD;
    for (int e = tid; e < NTOK * 8; e += 128) {
        int i = e >> 3, d4 = (e & 7) * 4;
        const float* p = base + i * QKVN + d4;
        *(float4*)&qsm[i][d4] = *(const float4*)p;
        *(float4*)&ksm[i][d4] = *(const float4*)(p + BDIM);
        *(float4*)&vsm[i][d4] = *(const float4*)(p + 2 * BDIM);
    }
    __syncthreads();

    // ---- Scores: S[16][64] per warp, K = 32 ----
    float acc[8][4];
#pragma unroll
    for (int nt = 0; nt < 8; nt++)
#pragma unroll
        for (int e = 0; e < 4; e++) acc[nt][e] = 0.0f;

#pragma unroll
    for (int k0 = 0; k0 < HD; k0 += 8) {
        uint32_t a[4];
        a[0] = cvt_tf32(qsm[m0 + g][k0 + tig]);
        a[1] = cvt_tf32(qsm[m0 + g + 8][k0 + tig]);
        a[2] = cvt_tf32(qsm[m0 + g][k0 + tig + 4]);
        a[3] = cvt_tf32(qsm[m0 + g + 8][k0 + tig + 4]);
#pragma unroll
        for (int nt = 0; nt < 8; nt++) {
            uint32_t b0 = cvt_tf32(ksm[nt * 8 + g][k0 + tig]);
            uint32_t b1 = cvt_tf32(ksm[nt * 8 + g][k0 + tig + 4]);
            mma_tf32(acc[nt], a, b0, b1);
        }
    }

    // ---- bias + mask + padding guards; row stats ----
    const float* cb = g_bias + ((size_t)(b & (NMASK - 1)) * HEADS + h) * NN;
    const int r0 = m0 + g, r1 = m0 + g + 8;
    float m0v = -1e30f, m1v = -1e30f;
#pragma unroll
    for (int nt = 0; nt < 8; nt++) {
        int j = nt * 8 + 2 * tig;
        float b00 = (r0 < NTOK && j < NTOK)     ? cb[r0 * NTOK + j]     : -1e30f;
        float b01 = (r0 < NTOK && j + 1 < NTOK) ? cb[r0 * NTOK + j + 1] : -1e30f;
        float b10 = (r1 < NTOK && j < NTOK)     ? cb[r1 * NTOK + j]     : -1e30f;
        float b11 = (r1 < NTOK && j + 1 < NTOK) ? cb[r1 * NTOK + j + 1] : -1e30f;
        acc[nt][0] = fmaf(acc[nt][0], scale, b00);
        acc[nt][1] = fmaf(acc[nt][1], scale, b01);
        acc[nt][2] = fmaf(acc[nt][2], scale, b10);
        acc[nt][3] = fmaf(acc[nt][3], scale, b11);
        m0v = fmaxf(m0v, fmaxf(acc[nt][0], acc[nt][1]));
        m1v = fmaxf(m1v, fmaxf(acc[nt][2], acc[nt][3]));
    }
    m0v = fmaxf(m0v, __shfl_xor_sync(0xffffffffu, m0v, 1));
    m0v = fmaxf(m0v, __shfl_xor_sync(0xffffffffu, m0v, 2));
    m1v = fmaxf(m1v, __shfl_xor_sync(0xffffffffu, m1v, 1));
    m1v = fmaxf(m1v, __shfl_xor_sync(0xffffffffu, m1v, 2));

    float s0 = 0.f, s1 = 0.f;
#pragma unroll
    for (int nt = 0; nt < 8; nt++) {
        acc[nt][0] = __expf(acc[nt][0] - m0v);
        acc[nt][1] = __expf(acc[nt][1] - m0v);
        acc[nt][2] = __expf(acc[nt][2] - m1v);
        acc[nt][3] = __expf(acc[nt][3] - m1v);
        s0 += acc[nt][0] + acc[nt][1];
        s1 += acc[nt][2] + acc[nt][3];
    }
    s0 += __shfl_xor_sync(0xffffffffu, s0, 1);
    s0 += __shfl_xor_sync(0xffffffffu, s0, 2);
    s1 += __shfl_xor_sync(0xffffffffu, s1, 1);
    s1 += __shfl_xor_sync(0xffffffffu, s1, 2);
    const float inv0 = 1.0f / s0, inv1 = 1.0f / s1;

#pragma unroll
    for (int nt = 0; nt < 8; nt++) {
        int j = nt * 8 + 2 * tig;
        float2 p0 = {round_tf32f(acc[nt][0] * inv0), round_tf32f(acc[nt][1] * inv0)};
        float2 p1 = {round_tf32f(acc[nt][2] * inv1), round_tf32f(acc[nt][3] * inv1)};
        *(float2*)&ps[w][g][j]     = p0;
        *(float2*)&ps[w][g + 8][j] = p1;
    }
    __syncwarp();

    // ---- PV: O[16][32] per warp, K = 64 ----
    float out[4][4];
#pragma unroll
    for (int nt = 0; nt < 4; nt++)
#pragma unroll
        for (int e = 0; e < 4; e++) out[nt][e] = 0.0f;

#pragma unroll
    for (int k0 = 0; k0 < 64; k0 += 8) {
        uint32_t a[4];
        a[0] = __float_as_uint(ps[w][g][k0 + tig]);
        a[1] = __float_as_uint(ps[w][g + 8][k0 + tig]);
        a[2] = __float_as_uint(ps[w][g][k0 + tig + 4]);
        a[3] = __float_as_uint(ps[w][g + 8][k0 + tig + 4]);
#pragma unroll
        for (int nt = 0; nt < 4; nt++) {
            uint32_t b0 = cvt_tf32(vsm[k0 + tig][nt * 8 + g]);
            uint32_t b1 = cvt_tf32(vsm[k0 + tig + 4][nt * 8 + g]);
            mma_tf32(out[nt], a, b0, b1);
        }
    }

    // ---- store (proj GEMM cvts A in-loop; no rounding needed here) ----
    float* outb = g_attn + (size_t)b * NTOK * BDIM + h * HD;
#pragma unroll
    for (int nt = 0; nt < 4; nt++) {
        int d0 = nt * 8 + 2 * tig;
        if (r0 < NTOK) {
            float2 o = {out[nt][0], out[nt][1]};
            *(float2*)(outb + (size_t)r0 * BDIM + d0) = o;
        }
        if (r1 < NTOK) {
            float2 o = {out[nt][2], out[nt][3]};
            *(float2*)(outb + (size_t)r1 * BDIM + d0) = o;
        }
    }
}

// ---------------------------------------------------------------------------
extern "C" void kernel_launch(void* const* d_in, const int* in_sizes, int n_in,
                              void* d_out, int out_size) {
    const float* x         = (const float*)d_in[0];  // [2048, 49, 384]
    const float* mask      = (const float*)d_in[1];  // [64, 49, 49]
    const float* qkv_w     = (const float*)d_in[2];  // [1152, 384]
    const float* qkv_b     = (const float*)d_in[3];  // [1152]
    const float* proj_w    = (const float*)d_in[4];  // [384, 384]
    const float* proj_b    = (const float*)d_in[5];  // [384]
    const float* rel_table = (const float*)d_in[6];  // [169, 12]
    const int*   rel_index = (const int*)d_in[7];    // [49, 49]
    float* out = (float*)d_out;                      // [2048, 49, 384]

    float *qkv_buf, *attn_buf, *wq, *wp;
    cudaGetSymbolAddress((void**)&qkv_buf, g_qkv);
    cudaGetSymbolAddress((void**)&attn_buf, g_attn);
    cudaGetSymbolAddress((void**)&wq, g_wq);
    cudaGetSymbolAddress((void**)&wp, g_wp);

    const int SMEM_GEMM = (3 * 128 * 20 + 3 * 128 * 20) * 4;  // 61440 B
    cudaFuncSetAttribute(tf32_gemm_abT_bias,
                         cudaFuncAttributeMaxDynamicSharedMemorySize, SMEM_GEMM);

    // 0) Prep: round weights to tf32; build combined bias+mask table.
    {
        int w4 = (QKVN * BDIM) / 4;
        round_tf32_kernel<<<(w4 + 255) / 256, 256>>>(qkv_w, wq, w4);
        int p4 = (BDIM * BDIM) / 4;
        round_tf32_kernel<<<(p4 + 255) / 256, 256>>>(proj_w, wp, p4);
        int bt = NMASK * HEADS * NN;
        bias_prep_kernel<<<(bt + 255) / 256, 256>>>(mask, rel_table, rel_index);
    }

    // 1) QKV GEMM: [100352, 384] @ [1152, 384]^T -> [100352, 1152]
    {
        dim3 grid(QKVN / 128, MROWS / 128);   // (9, 784)
        tf32_gemm_abT_bias<<<grid, 256, SMEM_GEMM>>>(x, wq, qkv_b, qkv_buf,
                                                     MROWS, QKVN, BDIM);
    }

    // 2) attention per (window, head), tensor-core path
    {
        dim3 grid(NWIN, HEADS);               // (2048, 12)
        attn_mma_kernel<<<grid, 128>>>();
    }

    // 3) proj GEMM: [100352, 384] @ [384, 384]^T -> [100352, 384]
    {
        dim3 grid(BDIM / 128, MROWS / 128);   // (3, 784)
        tf32_gemm_abT_bias<<<grid, 256, SMEM_GEMM>>>(attn_buf, wp, proj_b, out,
                                                     MROWS, BDIM, BDIM);
    }
}

// round 14
// speedup vs baseline: 2.2782x; 1.0412x over previous
#include <cuda_runtime.h>
#include <cuda_bf16.h>
#include <cstdint>

// ---------------------------------------------------------------------------
// WindowAttention (Swin): B=2048 windows, N=49 tokens, DIM=384, HEADS=12, hd=32
// R14: GEMM fragment loads via ldmatrix.x4 (b32-in-b16 trick): 24 scalar LDS
//      -> 6 LDSM per k-slice. Pipeline/attention/prep unchanged from R13.
// ---------------------------------------------------------------------------

#define BDIM   384
#define HEADS  12
#define HD     32
#define NTOK   49
#define NWIN   2048
#define NMASK  64
#define MROWS  (NWIN * NTOK)        // 100352
#define QKVN   (3 * BDIM)           // 1152
#define NN     (NTOK * NTOK)        // 2401

__device__ float g_qkv[(size_t)MROWS * QKVN];    // ~462 MB
__device__ float g_attn[(size_t)MROWS * BDIM];   // ~154 MB
__device__ float g_wq[QKVN * BDIM];              // qkv_w rounded
__device__ float g_wp[BDIM * BDIM];              // proj_w rounded
__device__ float g_bias[NMASK * HEADS * NN];     // mask + rel bias, 7.4 MB

__device__ __forceinline__ uint32_t cvt_tf32(float x) {
    uint32_t r;
    asm("cvt.rna.tf32.f32 %0, %1;" : "=r"(r) : "f"(x));
    return r;
}
__device__ __forceinline__ float round_tf32f(float x) {
    return __uint_as_float(cvt_tf32(x));
}
__device__ __forceinline__ uint32_t cvt_tf32_bits(uint32_t xb) {
    return cvt_tf32(__uint_as_float(xb));
}
__device__ __forceinline__ uint32_t smem_u32(const void* p) {
    uint32_t r;
    asm("{ .reg .u64 t; cvta.to.shared.u64 t, %1; cvt.u32.u64 %0, t; }"
        : "=r"(r) : "l"(p));
    return r;
}
__device__ __forceinline__ void mma_tf32(float* c, const uint32_t* a,
                                         uint32_t b0, uint32_t b1) {
    asm volatile(
        "mma.sync.aligned.m16n8k8.row.col.f32.tf32.tf32.f32 "
        "{%0,%1,%2,%3}, {%4,%5,%6,%7}, {%8,%9}, {%0,%1,%2,%3};"
        : "+f"(c[0]), "+f"(c[1]), "+f"(c[2]), "+f"(c[3])
        : "r"(a[0]), "r"(a[1]), "r"(a[2]), "r"(a[3]), "r"(b0), "r"(b1));
}
__device__ __forceinline__ void ldsm4(uint32_t& r0, uint32_t& r1,
                                      uint32_t& r2, uint32_t& r3,
                                      uint32_t addr) {
    asm volatile("ldmatrix.sync.aligned.m8n8.x4.shared.b16 {%0,%1,%2,%3}, [%4];"
                 : "=r"(r0), "=r"(r1), "=r"(r2), "=r"(r3) : "r"(addr));
}
#define CP_ASYNC16(dst_u32, src_ptr) \
    asm volatile("cp.async.cg.shared.global [%0], [%1], 16;" :: "r"(dst_u32), "l"(src_ptr))
#define CP_COMMIT() asm volatile("cp.async.commit_group;" ::: "memory")
#define CP_WAIT_G1() asm volatile("cp.async.wait_group 1;" ::: "memory")

// ---------------------------------------------------------------------------
// Prep kernels
// ---------------------------------------------------------------------------
__global__ void round_tf32_kernel(const float* __restrict__ src,
                                  float* __restrict__ dst, int n4) {
    int i = blockIdx.x * blockDim.x + threadIdx.x;
    if (i < n4) {
        float4 v = ((const float4*)src)[i];
        v.x = round_tf32f(v.x); v.y = round_tf32f(v.y);
        v.z = round_tf32f(v.z); v.w = round_tf32f(v.w);
        ((float4*)dst)[i] = v;
    }
}

__global__ void bias_prep_kernel(const float* __restrict__ mask,
                                 const float* __restrict__ rel_table,
                                 const int*   __restrict__ rel_index) {
    int idx = blockIdx.x * blockDim.x + threadIdx.x;
    const int total = NMASK * HEADS * NN;
    if (idx < total) {
        int e  = idx % NN;
        int wh = idx / NN;
        int h  = wh % HEADS;
        int w  = wh / HEADS;
        g_bias[idx] = mask[w * NN + e] + rel_table[rel_index[e] * HEADS + h];
    }
}

// ---------------------------------------------------------------------------
// TF32 GEMM: C[m][n]=sum_k tf32(A[m][k])*W[n][k]+bias[n]
// A raw fp32 (cvt'd post-ldmatrix), W pre-rounded tf32.
// 128x128x16 CTA tile, 8 warps (4x2) of 32x64, 3-stage cp.async,
// ONE __syncthreads per k-tile, ldmatrix.x4 fragment loads.
// ---------------------------------------------------------------------------
__global__ __launch_bounds__(256, 2)
void tf32_gemm_abT_bias(const float* __restrict__ A,
                        const float* __restrict__ W,
                        const float* __restrict__ bias,
                        float* __restrict__ C,
                        int M, int N, int K) {
    constexpr int BM = 128, BN = 128, BK = 16, LD = 20;
    extern __shared__ float smem[];
    float* As = smem;                   // [3][BM][LD]
    float* Bs = smem + 3 * BM * LD;     // [3][BN][LD]

    const int tid = threadIdx.x;
    const int bm = blockIdx.y * BM;
    const int bn = blockIdx.x * BN;
    const int lane = tid & 31;
    const int warp = tid >> 5;
    const int wm = (warp >> 1) * 32;
    const int wn = (warp & 1) * 64;
    const int g   = lane >> 2;
    const int tig = lane & 3;

    // ldmatrix per-lane source rows:
    //  A x4: m0 rows r0..r0+7 @k, m1 +8 rows @k, m2 rows @k+4, m3 +8 @k+4
    //   lane sel = lane>>3: row_local = (sel&1)*8 + (lane&7), col_off = (lane>>4)*4
    //  B x4: m0 nt rows @k, m1 nt rows @k+4, m2 nt+1 rows @k, m3 nt+1 rows @k+4
    //   row_local = (lane>>4)*8 + (lane&7), col_off = ((lane>>3)&1)*4
    const uint32_t aBase = smem_u32(As) +
        (uint32_t)(((wm + ((lane >> 3) & 1) * 8 + (lane & 7)) * LD +
                    (lane >> 4) * 4) * 4);
    const uint32_t bBase = smem_u32(Bs) +
        (uint32_t)(((wn + (lane >> 4) * 8 + (lane & 7)) * LD +
                    ((lane >> 3) & 1) * 4) * 4);

    float acc[2][8][4];
#pragma unroll
    for (int mt = 0; mt < 2; mt++)
#pragma unroll
        for (int nt = 0; nt < 8; nt++)
#pragma unroll
            for (int e = 0; e < 4; e++) acc[mt][nt][e] = 0.0f;

    const int KT = K / BK;

    auto load_stage = [&](int st, int kt) {
        const int k0 = kt * BK;
        float* as = As + st * (BM * LD);
        float* bs = Bs + st * (BN * LD);
#pragma unroll
        for (int i = 0; i < 2; i++) {
            int c = tid + i * 256;       // 0..511
            int r = c >> 2;              // 0..127
            int s4 = (c & 3) * 4;
            CP_ASYNC16(smem_u32(&as[r * LD + s4]),
                       A + (size_t)(bm + r) * K + k0 + s4);
            CP_ASYNC16(smem_u32(&bs[r * LD + s4]),
                       W + (size_t)(bn + r) * K + k0 + s4);
        }
    };

    auto compute = [&](int st) {
        const uint32_t aOff = aBase + (uint32_t)(st * BM * LD * 4);
        const uint32_t bOff = bBase + (uint32_t)(st * BN * LD * 4);
#pragma unroll
        for (int ks = 0; ks < 2; ks++) {
            uint32_t a[2][4], bf[8][2];
#pragma unroll
            for (int mt = 0; mt < 2; mt++) {
                ldsm4(a[mt][0], a[mt][1], a[mt][2], a[mt][3],
                      aOff + (uint32_t)((mt * 16 * LD + ks * 8) * 4));
                a[mt][0] = cvt_tf32_bits(a[mt][0]);
                a[mt][1] = cvt_tf32_bits(a[mt][1]);
                a[mt][2] = cvt_tf32_bits(a[mt][2]);
                a[mt][3] = cvt_tf32_bits(a[mt][3]);
            }
#pragma unroll
            for (int p = 0; p < 4; p++) {
                ldsm4(bf[2 * p][0], bf[2 * p][1], bf[2 * p + 1][0], bf[2 * p + 1][1],
                      bOff + (uint32_t)((p * 16 * LD + ks * 8) * 4));
            }
#pragma unroll
            for (int mt = 0; mt < 2; mt++)
#pragma unroll
                for (int nt = 0; nt < 8; nt++)
                    mma_tf32(acc[mt][nt], a[mt], bf[nt][0], bf[nt][1]);
        }
    };

    load_stage(0, 0); CP_COMMIT();
    load_stage(1, 1); CP_COMMIT();

    for (int kt = 0; kt < KT; kt++) {
        CP_WAIT_G1();
        __syncthreads();
        compute(kt % 3);
        if (kt + 2 < KT) load_stage((kt + 2) % 3, kt + 2);
        CP_COMMIT();
    }

#pragma unroll
    for (int mt = 0; mt < 2; mt++) {
#pragma unroll
        for (int nt = 0; nt < 8; nt++) {
            int row = bm + wm + mt * 16 + g;
            int col = bn + wn + nt * 8 + 2 * tig;
            float b0 = bias[col], b1 = bias[col + 1];
            float2 o0 = {acc[mt][nt][0] + b0, acc[mt][nt][1] + b1};
            float2 o1 = {acc[mt][nt][2] + b0, acc[mt][nt][3] + b1};
            *(float2*)(C + (size_t)row * N + col) = o0;
            *(float2*)(C + (size_t)(row + 8) * N + col) = o1;
        }
    }
}

// ---------------------------------------------------------------------------
// Tensor-core attention per (window, head). 128 threads = 4 warps.
// Warp w owns rows [16w, 16w+16). Pad 49 -> 64.
// ---------------------------------------------------------------------------
__global__ __launch_bounds__(128)
void attn_mma_kernel() {
    const int b = blockIdx.x;
    const int h = blockIdx.y;

    __shared__ float qsm[64][36];
    __shared__ float ksm[64][36];
    __shared__ float vsm[64][36];
    __shared__ float ps[4][16][68];

    const int tid = threadIdx.x;
    const int lane = tid & 31;
    const int w = tid >> 5;
    const int g = lane >> 2;          // 0..7
    const int tig = lane & 3;         // 0..3
    const int m0 = w * 16;
    const float scale = 0.17677669529663687f;  // 32^-0.5

    for (int e = tid; e < (64 - NTOK) * 9; e += 128) {
        int i = NTOK + e / 9, c4 = (e % 9) * 4;
        float4 z = {0.f, 0.f, 0.f, 0.f};
        *(float4*)&qsm[i][c4] = z;
        *(float4*)&ksm[i][c4] = z;
        *(float4*)&vsm[i][c4] = z;
    }
    const float* base = g_qkv + (size_t)b * NTOK * QKVN + h * HD;
    for (int e = tid; e < NTOK * 8; e += 128) {
        int i = e >> 3, d4 = (e & 7) * 4;
        const float* p = base + i * QKVN + d4;
        *(float4*)&qsm[i][d4] = *(const float4*)p;
        *(float4*)&ksm[i][d4] = *(const float4*)(p + BDIM);
        *(float4*)&vsm[i][d4] = *(const float4*)(p + 2 * BDIM);
    }
    __syncthreads();

    // ---- Scores: S[16][64] per warp, K = 32 ----
    float acc[8][4];
#pragma unroll
    for (int nt = 0; nt < 8; nt++)
#pragma unroll
        for (int e = 0; e < 4; e++) acc[nt][e] = 0.0f;

#pragma unroll
    for (int k0 = 0; k0 < HD; k0 += 8) {
        uint32_t a[4];
        a[0] = cvt_tf32(qsm[m0 + g][k0 + tig]);
        a[1] = cvt_tf32(qsm[m0 + g + 8][k0 + tig]);
        a[2] = cvt_tf32(qsm[m0 + g][k0 + tig + 4]);
        a[3] = cvt_tf32(qsm[m0 + g + 8][k0 + tig + 4]);
#pragma unroll
        for (int nt = 0; nt < 8; nt++) {
            uint32_t b0 = cvt_tf32(ksm[nt * 8 + g][k0 + tig]);
            uint32_t b1 = cvt_tf32(ksm[nt * 8 + g][k0 + tig + 4]);
            mma_tf32(acc[nt], a, b0, b1);
        }
    }

    // ---- bias + mask + padding guards; row stats ----
    const float* cb = g_bias + ((size_t)(b & (NMASK - 1)) * HEADS + h) * NN;
    const int r0 = m0 + g, r1 = m0 + g + 8;
    float m0v = -1e30f, m1v = -1e30f;
#pragma unroll
    for (int nt = 0; nt < 8; nt++) {
        int j = nt * 8 + 2 * tig;
        float b00 = (r0 < NTOK && j < NTOK)     ? cb[r0 * NTOK + j]     : -1e30f;
        float b01 = (r0 < NTOK && j + 1 < NTOK) ? cb[r0 * NTOK + j + 1] : -1e30f;
        float b10 = (r1 < NTOK && j < NTOK)     ? cb[r1 * NTOK + j]     : -1e30f;
        float b11 = (r1 < NTOK && j + 1 < NTOK) ? cb[r1 * NTOK + j + 1] : -1e30f;
        acc[nt][0] = fmaf(acc[nt][0], scale, b00);
        acc[nt][1] = fmaf(acc[nt][1], scale, b01);
        acc[nt][2] = fmaf(acc[nt][2], scale, b10);
        acc[nt][3] = fmaf(acc[nt][3], scale, b11);
        m0v = fmaxf(m0v, fmaxf(acc[nt][0], acc[nt][1]));
        m1v = fmaxf(m1v, fmaxf(acc[nt][2], acc[nt][3]));
    }
    m0v = fmaxf(m0v, __shfl_xor_sync(0xffffffffu, m0v, 1));
    m0v = fmaxf(m0v, __shfl_xor_sync(0xffffffffu, m0v, 2));
    m1v = fmaxf(m1v, __shfl_xor_sync(0xffffffffu, m1v, 1));
    m1v = fmaxf(m1v, __shfl_xor_sync(0xffffffffu, m1v, 2));

    float s0 = 0.f, s1 = 0.f;
#pragma unroll
    for (int nt = 0; nt < 8; nt++) {
        acc[nt][0] = __expf(acc[nt][0] - m0v);
        acc[nt][1] = __expf(acc[nt][1] - m0v);
        acc[nt][2] = __expf(acc[nt][2] - m1v);
        acc[nt][3] = __expf(acc[nt][3] - m1v);
        s0 += acc[nt][0] + acc[nt][1];
        s1 += acc[nt][2] + acc[nt][3];
    }
    s0 += __shfl_xor_sync(0xffffffffu, s0, 1);
    s0 += __shfl_xor_sync(0xffffffffu, s0, 2);
    s1 += __shfl_xor_sync(0xffffffffu, s1, 1);
    s1 += __shfl_xor_sync(0xffffffffu, s1, 2);
    const float inv0 = 1.0f / s0, inv1 = 1.0f / s1;

#pragma unroll
    for (int nt = 0; nt < 8; nt++) {
        int j = nt * 8 + 2 * tig;
        float2 p0 = {round_tf32f(acc[nt][0] * inv0), round_tf32f(acc[nt][1] * inv0)};
        float2 p1 = {round_tf32f(acc[nt][2] * inv1), round_tf32f(acc[nt][3] * inv1)};
        *(float2*)&ps[w][g][j]     = p0;
        *(float2*)&ps[w][g + 8][j] = p1;
    }
    __syncwarp();

    // ---- PV: O[16][32] per warp, K = 64 ----
    float out[4][4];
#pragma unroll
    for (int nt = 0; nt < 4; nt++)
#pragma unroll
        for (int e = 0; e < 4; e++) out[nt][e] = 0.0f;

#pragma unroll
    for (int k0 = 0; k0 < 64; k0 += 8) {
        uint32_t a[4];
        a[0] = __float_as_uint(ps[w][g][k0 + tig]);
        a[1] = __float_as_uint(ps[w][g + 8][k0 + tig]);
        a[2] = __float_as_uint(ps[w][g][k0 + tig + 4]);
        a[3] = __float_as_uint(ps[w][g + 8][k0 + tig + 4]);
#pragma unroll
        for (int nt = 0; nt < 4; nt++) {
            uint32_t b0 = cvt_tf32(vsm[k0 + tig][nt * 8 + g]);
            uint32_t b1 = cvt_tf32(vsm[k0 + tig + 4][nt * 8 + g]);
            mma_tf32(out[nt], a, b0, b1);
        }
    }

    // ---- store (proj GEMM cvts A in-loop; no rounding needed here) ----
    float* outb = g_attn + (size_t)b * NTOK * BDIM + h * HD;
#pragma unroll
    for (int nt = 0; nt < 4; nt++) {
        int d0 = nt * 8 + 2 * tig;
        if (r0 < NTOK) {
            float2 o = {out[nt][0], out[nt][1]};
            *(float2*)(outb + (size_t)r0 * BDIM + d0) = o;
        }
        if (r1 < NTOK) {
            float2 o = {out[nt][2], out[nt][3]};
            *(float2*)(outb + (size_t)r1 * BDIM + d0) = o;
        }
    }
}

// ---------------------------------------------------------------------------
extern "C" void kernel_launch(void* const* d_in, const int* in_sizes, int n_in,
                              void* d_out, int out_size) {
    const float* x         = (const float*)d_in[0];  // [2048, 49, 384]
    const float* mask      = (const float*)d_in[1];  // [64, 49, 49]
    const float* qkv_w     = (const float*)d_in[2];  // [1152, 384]
    const float* qkv_b     = (const float*)d_in[3];  // [1152]
    const float* proj_w    = (const float*)d_in[4];  // [384, 384]
    const float* proj_b    = (const float*)d_in[5];  // [384]
    const float* rel_table = (const float*)d_in[6];  // [169, 12]
    const int*   rel_index = (const int*)d_in[7];    // [49, 49]
    float* out = (float*)d_out;                      // [2048, 49, 384]

    float *qkv_buf, *attn_buf, *wq, *wp;
    cudaGetSymbolAddress((void**)&qkv_buf, g_qkv);
    cudaGetSymbolAddress((void**)&attn_buf, g_attn);
    cudaGetSymbolAddress((void**)&wq, g_wq);
    cudaGetSymbolAddress((void**)&wp, g_wp);

    const int SMEM_GEMM = (3 * 128 * 20 + 3 * 128 * 20) * 4;  // 61440 B
    cudaFuncSetAttribute(tf32_gemm_abT_bias,
                         cudaFuncAttributeMaxDynamicSharedMemorySize, SMEM_GEMM);

    // 0) Prep: round weights to tf32; build combined bias+mask table.
    {
        int w4 = (QKVN * BDIM) / 4;
        round_tf32_kernel<<<(w4 + 255) / 256, 256>>>(qkv_w, wq, w4);
        int p4 = (BDIM * BDIM) / 4;
        round_tf32_kernel<<<(p4 + 255) / 256, 256>>>(proj_w, wp, p4);
        int bt = NMASK * HEADS * NN;
        bias_prep_kernel<<<(bt + 255) / 256, 256>>>(mask, rel_table, rel_index);
    }

    // 1) QKV GEMM: [100352, 384] @ [1152, 384]^T -> [100352, 1152]
    {
        dim3 grid(QKVN / 128, MROWS / 128);   // (9, 784)
        tf32_gemm_abT_bias<<<grid, 256, SMEM_GEMM>>>(x, wq, qkv_b, qkv_buf,
                                                     MROWS, QKVN, BDIM);
    }

    // 2) attention per (window, head), tensor-core path
    {
        dim3 grid(NWIN, HEADS);               // (2048, 12)
        attn_mma_kernel<<<grid, 128>>>();
    }

    // 3) proj GEMM: [100352, 384] @ [384, 384]^T -> [100352, 384]
    {
        dim3 grid(BDIM / 128, MROWS / 128);   // (3, 784)
        tf32_gemm_abT_bias<<<grid, 256, SMEM_GEMM>>>(attn_buf, wp, proj_b, out,
                                                     MROWS, BDIM, BDIM);
    }
}

// round 17
// speedup vs baseline: 2.4296x; 1.0664x over previous
#include <cuda_runtime.h>
#include <cuda_bf16.h>
#include <cstdint>

// ---------------------------------------------------------------------------
// WindowAttention (Swin): B=2048 windows, N=49 tokens, DIM=384, HEADS=12, hd=32
// R15: GEMM BK 16->32 (12 k-tiles, 12 barriers) on the proven 3-stage
//      single-barrier ldmatrix pipeline. Attention/prep unchanged from R14.
// ---------------------------------------------------------------------------

#define BDIM   384
#define HEADS  12
#define HD     32
#define NTOK   49
#define NWIN   2048
#define NMASK  64
#define MROWS  (NWIN * NTOK)        // 100352
#define QKVN   (3 * BDIM)           // 1152
#define NN     (NTOK * NTOK)        // 2401

__device__ float g_qkv[(size_t)MROWS * QKVN];    // ~462 MB
__device__ float g_attn[(size_t)MROWS * BDIM];   // ~154 MB
__device__ float g_wq[QKVN * BDIM];              // qkv_w rounded
__device__ float g_wp[BDIM * BDIM];              // proj_w rounded
__device__ float g_bias[NMASK * HEADS * NN];     // mask + rel bias, 7.4 MB

__device__ __forceinline__ uint32_t cvt_tf32(float x) {
    uint32_t r;
    asm("cvt.rna.tf32.f32 %0, %1;" : "=r"(r) : "f"(x));
    return r;
}
__device__ __forceinline__ float round_tf32f(float x) {
    return __uint_as_float(cvt_tf32(x));
}
__device__ __forceinline__ uint32_t cvt_tf32_bits(uint32_t xb) {
    return cvt_tf32(__uint_as_float(xb));
}
__device__ __forceinline__ uint32_t smem_u32(const void* p) {
    uint32_t r;
    asm("{ .reg .u64 t; cvta.to.shared.u64 t, %1; cvt.u32.u64 %0, t; }"
        : "=r"(r) : "l"(p));
    return r;
}
__device__ __forceinline__ void mma_tf32(float* c, const uint32_t* a,
                                         uint32_t b0, uint32_t b1) {
    asm volatile(
        "mma.sync.aligned.m16n8k8.row.col.f32.tf32.tf32.f32 "
        "{%0,%1,%2,%3}, {%4,%5,%6,%7}, {%8,%9}, {%0,%1,%2,%3};"
        : "+f"(c[0]), "+f"(c[1]), "+f"(c[2]), "+f"(c[3])
        : "r"(a[0]), "r"(a[1]), "r"(a[2]), "r"(a[3]), "r"(b0), "r"(b1));
}
__device__ __forceinline__ void ldsm4(uint32_t& r0, uint32_t& r1,
                                      uint32_t& r2, uint32_t& r3,
                                      uint32_t addr) {
    asm volatile("ldmatrix.sync.aligned.m8n8.x4.shared.b16 {%0,%1,%2,%3}, [%4];"
                 : "=r"(r0), "=r"(r1), "=r"(r2), "=r"(r3) : "r"(addr));
}
#define CP_ASYNC16(dst_u32, src_ptr) \
    asm volatile("cp.async.cg.shared.global [%0], [%1], 16;" :: "r"(dst_u32), "l"(src_ptr))
#define CP_COMMIT() asm volatile("cp.async.commit_group;" ::: "memory")
#define CP_WAIT_G1() asm volatile("cp.async.wait_group 1;" ::: "memory")

// ---------------------------------------------------------------------------
// Prep kernels
// ---------------------------------------------------------------------------
__global__ void round_tf32_kernel(const float* __restrict__ src,
                                  float* __restrict__ dst, int n4) {
    int i = blockIdx.x * blockDim.x + threadIdx.x;
    if (i < n4) {
        float4 v = ((const float4*)src)[i];
        v.x = round_tf32f(v.x); v.y = round_tf32f(v.y);
        v.z = round_tf32f(v.z); v.w = round_tf32f(v.w);
        ((float4*)dst)[i] = v;
    }
}

__global__ void bias_prep_kernel(const float* __restrict__ mask,
                                 const float* __restrict__ rel_table,
                                 const int*   __restrict__ rel_index) {
    int idx = blockIdx.x * blockDim.x + threadIdx.x;
    const int total = NMASK * HEADS * NN;
    if (idx < total) {
        int e  = idx % NN;
        int wh = idx / NN;
        int h  = wh % HEADS;
        int w  = wh / HEADS;
        g_bias[idx] = mask[w * NN + e] + rel_table[rel_index[e] * HEADS + h];
    }
}

// ---------------------------------------------------------------------------
// TF32 GEMM: C[m][n]=sum_k tf32(A[m][k])*W[n][k]+bias[n]
// A raw fp32 (cvt'd post-ldmatrix), W pre-rounded tf32.
// 128x128x32 CTA tile, 8 warps (4x2) of 32x64, 3-stage cp.async,
// ONE __syncthreads per k-tile (12 total), ldmatrix.x4 fragment loads.
// ---------------------------------------------------------------------------
__global__ __launch_bounds__(256, 2)
void tf32_gemm_abT_bias(const float* __restrict__ A,
                        const float* __restrict__ W,
                        const float* __restrict__ bias,
                        float* __restrict__ C,
                        int M, int N, int K) {
    constexpr int BM = 128, BN = 128, BK = 32, LD = 36;
    extern __shared__ float smem[];
    float* As = smem;                   // [3][BM][LD]
    float* Bs = smem + 3 * BM * LD;     // [3][BN][LD]

    const int tid = threadIdx.x;
    const int bm = blockIdx.y * BM;
    const int bn = blockIdx.x * BN;
    const int lane = tid & 31;
    const int warp = tid >> 5;
    const int wm = (warp >> 1) * 32;
    const int wn = (warp & 1) * 64;
    const int g   = lane >> 2;
    const int tig = lane & 3;

    // ldmatrix lane->address mapping (same scheme as R14, LD=36):
    const uint32_t aBase = smem_u32(As) +
        (uint32_t)(((wm + ((lane >> 3) & 1) * 8 + (lane & 7)) * LD +
                    (lane >> 4) * 4) * 4);
    const uint32_t bBase = smem_u32(Bs) +
        (uint32_t)(((wn + (lane >> 4) * 8 + (lane & 7)) * LD +
                    ((lane >> 3) & 1) * 4) * 4);

    float acc[2][8][4];
#pragma unroll
    for (int mt = 0; mt < 2; mt++)
#pragma unroll
        for (int nt = 0; nt < 8; nt++)
#pragma unroll
            for (int e = 0; e < 4; e++) acc[mt][nt][e] = 0.0f;

    const int KT = K / BK;   // 12

    auto load_stage = [&](int st, int kt) {
        const int k0 = kt * BK;
        float* as = As + st * (BM * LD);
        float* bs = Bs + st * (BN * LD);
#pragma unroll
        for (int i = 0; i < 4; i++) {
            int idx = tid + i * 256;      // 0..1023
            int r = idx >> 3;             // 0..127
            int s4 = (idx & 7) * 4;       // 0,4,..,28
            CP_ASYNC16(smem_u32(&as[r * LD + s4]),
                       A + (size_t)(bm + r) * K + k0 + s4);
            CP_ASYNC16(smem_u32(&bs[r * LD + s4]),
                       W + (size_t)(bn + r) * K + k0 + s4);
        }
    };

    auto compute = [&](int st) {
        const uint32_t aOff = aBase + (uint32_t)(st * BM * LD * 4);
        const uint32_t bOff = bBase + (uint32_t)(st * BN * LD * 4);
#pragma unroll
        for (int ks = 0; ks < 4; ks++) {
            uint32_t a[2][4], bf[8][2];
#pragma unroll
            for (int mt = 0; mt < 2; mt++) {
                ldsm4(a[mt][0], a[mt][1], a[mt][2], a[mt][3],
                      aOff + (uint32_t)((mt * 16 * LD + ks * 8) * 4));
                a[mt][0] = cvt_tf32_bits(a[mt][0]);
                a[mt][1] = cvt_tf32_bits(a[mt][1]);
                a[mt][2] = cvt_tf32_bits(a[mt][2]);
                a[mt][3] = cvt_tf32_bits(a[mt][3]);
            }
#pragma unroll
            for (int p = 0; p < 4; p++) {
                ldsm4(bf[2 * p][0], bf[2 * p][1], bf[2 * p + 1][0], bf[2 * p + 1][1],
                      bOff + (uint32_t)((p * 16 * LD + ks * 8) * 4));
            }
#pragma unroll
            for (int mt = 0; mt < 2; mt++)
#pragma unroll
                for (int nt = 0; nt < 8; nt++)
                    mma_tf32(acc[mt][nt], a[mt], bf[nt][0], bf[nt][1]);
        }
    };

    load_stage(0, 0); CP_COMMIT();
    load_stage(1, 1); CP_COMMIT();

    for (int kt = 0; kt < KT; kt++) {
        CP_WAIT_G1();
        __syncthreads();
        compute(kt % 3);
        if (kt + 2 < KT) load_stage((kt + 2) % 3, kt + 2);
        CP_COMMIT();
    }

#pragma unroll
    for (int mt = 0; mt < 2; mt++) {
#pragma unroll
        for (int nt = 0; nt < 8; nt++) {
            int row = bm + wm + mt * 16 + g;
            int col = bn + wn + nt * 8 + 2 * tig;
            float b0 = bias[col], b1 = bias[col + 1];
            float2 o0 = {acc[mt][nt][0] + b0, acc[mt][nt][1] + b1};
            float2 o1 = {acc[mt][nt][2] + b0, acc[mt][nt][3] + b1};
            *(float2*)(C + (size_t)row * N + col) = o0;
            *(float2*)(C + (size_t)(row + 8) * N + col) = o1;
        }
    }
}

// ---------------------------------------------------------------------------
// Tensor-core attention per (window, head). 128 threads = 4 warps.
// Warp w owns rows [16w, 16w+16). Pad 49 -> 64.
// ---------------------------------------------------------------------------
__global__ __launch_bounds__(128)
void attn_mma_kernel() {
    const int b = blockIdx.x;
    const int h = blockIdx.y;

    __shared__ float qsm[64][36];
    __shared__ float ksm[64][36];
    __shared__ float vsm[64][36];
    __shared__ float ps[4][16][68];

    const int tid = threadIdx.x;
    const int lane = tid & 31;
    const int w = tid >> 5;
    const int g = lane >> 2;          // 0..7
    const int tig = lane & 3;         // 0..3
    const int m0 = w * 16;
    const float scale = 0.17677669529663687f;  // 32^-0.5

    for (int e = tid; e < (64 - NTOK) * 9; e += 128) {
        int i = NTOK + e / 9, c4 = (e % 9) * 4;
        float4 z = {0.f, 0.f, 0.f, 0.f};
        *(float4*)&qsm[i][c4] = z;
        *(float4*)&ksm[i][c4] = z;
        *(float4*)&vsm[i][c4] = z;
    }
    const float* base = g_qkv + (size_t)b * NTOK * QKVN + h * HD;
    for (int e = tid; e < NTOK * 8; e += 128) {
        int i = e >> 3, d4 = (e & 7) * 4;
        const float* p = base + i * QKVN + d4;
        *(float4*)&qsm[i][d4] = *(const float4*)p;
        *(float4*)&ksm[i][d4] = *(const float4*)(p + BDIM);
        *(float4*)&vsm[i][d4] = *(const float4*)(p + 2 * BDIM);
    }
    __syncthreads();

    // ---- Scores: S[16][64] per warp, K = 32 ----
    float acc[8][4];
#pragma unroll
    for (int nt = 0; nt < 8; nt++)
#pragma unroll
        for (int e = 0; e < 4; e++) acc[nt][e] = 0.0f;

#pragma unroll
    for (int k0 = 0; k0 < HD; k0 += 8) {
        uint32_t a[4];
        a[0] = cvt_tf32(qsm[m0 + g][k0 + tig]);
        a[1] = cvt_tf32(qsm[m0 + g + 8][k0 + tig]);
        a[2] = cvt_tf32(qsm[m0 + g][k0 + tig + 4]);
        a[3] = cvt_tf32(qsm[m0 + g + 8][k0 + tig + 4]);
#pragma unroll
        for (int nt = 0; nt < 8; nt++) {
            uint32_t b0 = cvt_tf32(ksm[nt * 8 + g][k0 + tig]);
            uint32_t b1 = cvt_tf32(ksm[nt * 8 + g][k0 + tig + 4]);
            mma_tf32(acc[nt], a, b0, b1);
        }
    }

    // ---- bias + mask + padding guards; row stats ----
    const float* cb = g_bias + ((size_t)(b & (NMASK - 1)) * HEADS + h) * NN;
    const int r0 = m0 + g, r1 = m0 + g + 8;
    float m0v = -1e30f, m1v = -1e30f;
#pragma unroll
    for (int nt = 0; nt < 8; nt++) {
        int j = nt * 8 + 2 * tig;
        float b00 = (r0 < NTOK && j < NTOK)     ? cb[r0 * NTOK + j]     : -1e30f;
        float b01 = (r0 < NTOK && j + 1 < NTOK) ? cb[r0 * NTOK + j + 1] : -1e30f;
        float b10 = (r1 < NTOK && j < NTOK)     ? cb[r1 * NTOK + j]     : -1e30f;
        float b11 = (r1 < NTOK && j + 1 < NTOK) ? cb[r1 * NTOK + j + 1] : -1e30f;
        acc[nt][0] = fmaf(acc[nt][0], scale, b00);
        acc[nt][1] = fmaf(acc[nt][1], scale, b01);
        acc[nt][2] = fmaf(acc[nt][2], scale, b10);
        acc[nt][3] = fmaf(acc[nt][3], scale, b11);
        m0v = fmaxf(m0v, fmaxf(acc[nt][0], acc[nt][1]));
        m1v = fmaxf(m1v, fmaxf(acc[nt][2], acc[nt][3]));
    }
    m0v = fmaxf(m0v, __shfl_xor_sync(0xffffffffu, m0v, 1));
    m0v = fmaxf(m0v, __shfl_xor_sync(0xffffffffu, m0v, 2));
    m1v = fmaxf(m1v, __shfl_xor_sync(0xffffffffu, m1v, 1));
    m1v = fmaxf(m1v, __shfl_xor_sync(0xffffffffu, m1v, 2));

    float s0 = 0.f, s1 = 0.f;
#pragma unroll
    for (int nt = 0; nt < 8; nt++) {
        acc[nt][0] = __expf(acc[nt][0] - m0v);
        acc[nt][1] = __expf(acc[nt][1] - m0v);
        acc[nt][2] = __expf(acc[nt][2] - m1v);
        acc[nt][3] = __expf(acc[nt][3] - m1v);
        s0 += acc[nt][0] + acc[nt][1];
        s1 += acc[nt][2] + acc[nt][3];
    }
    s0 += __shfl_xor_sync(0xffffffffu, s0, 1);
    s0 += __shfl_xor_sync(0xffffffffu, s0, 2);
    s1 += __shfl_xor_sync(0xffffffffu, s1, 1);
    s1 += __shfl_xor_sync(0xffffffffu, s1, 2);
    const float inv0 = 1.0f / s0, inv1 = 1.0f / s1;

#pragma unroll
    for (int nt = 0; nt < 8; nt++) {
        int j = nt * 8 + 2 * tig;
        float2 p0 = {round_tf32f(acc[nt][0] * inv0), round_tf32f(acc[nt][1] * inv0)};
        float2 p1 = {round_tf32f(acc[nt][2] * inv1), round_tf32f(acc[nt][3] * inv1)};
        *(float2*)&ps[w][g][j]     = p0;
        *(float2*)&ps[w][g + 8][j] = p1;
    }
    __syncwarp();

    // ---- PV: O[16][32] per warp, K = 64 ----
    float out[4][4];
#pragma unroll
    for (int nt = 0; nt < 4; nt++)
#pragma unroll
        for (int e = 0; e < 4; e++) out[nt][e] = 0.0f;

#pragma unroll
    for (int k0 = 0; k0 < 64; k0 += 8) {
        uint32_t a[4];
        a[0] = __float_as_uint(ps[w][g][k0 + tig]);
        a[1] = __float_as_uint(ps[w][g + 8][k0 + tig]);
        a[2] = __float_as_uint(ps[w][g][k0 + tig + 4]);
        a[3] = __float_as_uint(ps[w][g + 8][k0 + tig + 4]);
#pragma unroll
        for (int nt = 0; nt < 4; nt++) {
            uint32_t b0 = cvt_tf32(vsm[k0 + tig][nt * 8 + g]);
            uint32_t b1 = cvt_tf32(vsm[k0 + tig + 4][nt * 8 + g]);
            mma_tf32(out[nt], a, b0, b1);
        }
    }

    // ---- store (proj GEMM cvts A in-loop) ----
    float* outb = g_attn + (size_t)b * NTOK * BDIM + h * HD;
#pragma unroll
    for (int nt = 0; nt < 4; nt++) {
        int d0 = nt * 8 + 2 * tig;
        if (r0 < NTOK) {
            float2 o = {out[nt][0], out[nt][1]};
            *(float2*)(outb + (size_t)r0 * BDIM + d0) = o;
        }
        if (r1 < NTOK) {
            float2 o = {out[nt][2], out[nt][3]};
            *(float2*)(outb + (size_t)r1 * BDIM + d0) = o;
        }
    }
}

// ---------------------------------------------------------------------------
extern "C" void kernel_launch(void* const* d_in, const int* in_sizes, int n_in,
                              void* d_out, int out_size) {
    const float* x         = (const float*)d_in[0];  // [2048, 49, 384]
    const float* mask      = (const float*)d_in[1];  // [64, 49, 49]
    const float* qkv_w     = (const float*)d_in[2];  // [1152, 384]
    const float* qkv_b     = (const float*)d_in[3];  // [1152]
    const float* proj_w    = (const float*)d_in[4];  // [384, 384]
    const float* proj_b    = (const float*)d_in[5];  // [384]
    const float* rel_table = (const float*)d_in[6];  // [169, 12]
    const int*   rel_index = (const int*)d_in[7];    // [49, 49]
    float* out = (float*)d_out;                      // [2048, 49, 384]

    float *qkv_buf, *attn_buf, *wq, *wp;
    cudaGetSymbolAddress((void**)&qkv_buf, g_qkv);
    cudaGetSymbolAddress((void**)&attn_buf, g_attn);
    cudaGetSymbolAddress((void**)&wq, g_wq);
    cudaGetSymbolAddress((void**)&wp, g_wp);

    const int SMEM_GEMM = (3 * 128 * 36 + 3 * 128 * 36) * 4;  // 110592 B
    cudaFuncSetAttribute(tf32_gemm_abT_bias,
                         cudaFuncAttributeMaxDynamicSharedMemorySize, SMEM_GEMM);

    // 0) Prep: round weights to tf32; build combined bias+mask table.
    {
        int w4 = (QKVN * BDIM) / 4;
        round_tf32_kernel<<<(w4 + 255) / 256, 256>>>(qkv_w, wq, w4);
        int p4 = (BDIM * BDIM) / 4;
        round_tf32_kernel<<<(p4 + 255) / 256, 256>>>(proj_w, wp, p4);
        int bt = NMASK * HEADS * NN;
        bias_prep_kernel<<<(bt + 255) / 256, 256>>>(mask, rel_table, rel_index);
    }

    // 1) QKV GEMM: [100352, 384] @ [1152, 384]^T -> [100352, 1152]
    {
        dim3 grid(QKVN / 128, MROWS / 128);   // (9, 784)
        tf32_gemm_abT_bias<<<grid, 256, SMEM_GEMM>>>(x, wq, qkv_b, qkv_buf,
                                                     MROWS, QKVN, BDIM);
    }

    // 2) attention per (window, head), tensor-core path
    {
        dim3 grid(NWIN, HEADS);               // (2048, 12)
        attn_mma_kernel<<<grid, 128>>>();
    }

    // 3) proj GEMM: [100352, 384] @ [384, 384]^T -> [100352, 384]
    {
        dim3 grid(BDIM / 128, MROWS / 128);   // (3, 784)
        tf32_gemm_abT_bias<<<grid, 256, SMEM_GEMM>>>(attn_buf, wp, proj_b, out,
                                                     MROWS, BDIM, BDIM);
    }
}